// round 2
// baseline (speedup 1.0000x reference)
#include <cuda_runtime.h>
#include <math.h>

#define B_  4
#define C_  256
#define CI_ 128
#define NQ_ 8192
#define NKV_ 2048

// scratch (no cudaMalloc allowed)
__device__ float d_theta[(size_t)B_ * NQ_ * CI_];   // (b, n, ci)
__device__ float d_key  [(size_t)B_ * NKV_ * CI_];  // (b, m, ci)  pooled phi
__device__ float d_val  [(size_t)B_ * NKV_ * CI_];  // (b, m, ci)  pooled g
__device__ float d_yy   [(size_t)B_ * CI_ * NQ_];   // (b, ci, n)

// ---------------------------------------------------------------------------
// Kernel A: theta = conv1x1(x, theta_w) + theta_b  -> d_theta (b, n, ci)
// grid (NQ/64, B), 256 threads. Tile: 64 n x 128 o, K tiled by 64.
// ---------------------------------------------------------------------------
__global__ void conv_theta_kernel(const float* __restrict__ x,
                                  const float* __restrict__ tw,
                                  const float* __restrict__ tb) {
    extern __shared__ float sm[];
    float* xs = sm;              // [64][68]
    float* ws = sm + 64 * 68;    // [128][68]
    const int b = blockIdx.y;
    const int nbase = blockIdx.x * 64;
    const int tid = threadIdx.x;
    const int ot = tid >> 3;     // 0..31 -> 4 o each (128 o)
    const int nt = tid & 7;      // 0..7  -> 8 n each (64 n)

    float acc[4][8];
#pragma unroll
    for (int i = 0; i < 4; i++)
#pragma unroll
        for (int k = 0; k < 8; k++) acc[i][k] = 0.f;

    for (int c0 = 0; c0 < C_; c0 += 64) {
        __syncthreads();
#pragma unroll
        for (int u = 0; u < 4; u++) {
            int idx = u * 256 + tid;
            int cc = idx >> 4, j4 = idx & 15;
            *(float4*)&xs[cc * 68 + j4 * 4] =
                *(const float4*)&x[((size_t)b * C_ + c0 + cc) * NQ_ + nbase + j4 * 4];
        }
#pragma unroll
        for (int u = 0; u < 8; u++) {
            int idx = u * 256 + tid;
            int oo = idx >> 4, c4 = idx & 15;
            *(float4*)&ws[oo * 68 + c4 * 4] =
                *(const float4*)&tw[oo * C_ + c0 + c4 * 4];
        }
        __syncthreads();
#pragma unroll 4
        for (int cc = 0; cc < 64; cc++) {
            float wv[4];
#pragma unroll
            for (int i = 0; i < 4; i++) wv[i] = ws[(ot * 4 + i) * 68 + cc];
            float4 xa = *(float4*)&xs[cc * 68 + nt * 8];
            float4 xb = *(float4*)&xs[cc * 68 + nt * 8 + 4];
            float xv[8] = {xa.x, xa.y, xa.z, xa.w, xb.x, xb.y, xb.z, xb.w};
#pragma unroll
            for (int i = 0; i < 4; i++)
#pragma unroll
                for (int k = 0; k < 8; k++) acc[i][k] += wv[i] * xv[k];
        }
    }
    // stage through smem for coalesced (n, ci) write
    __syncthreads();
    float* st = sm;  // [64][132]
#pragma unroll
    for (int i = 0; i < 4; i++) {
        float bias = tb[ot * 4 + i];
#pragma unroll
        for (int k = 0; k < 8; k++)
            st[(nt * 8 + k) * 132 + ot * 4 + i] = acc[i][k] + bias;
    }
    __syncthreads();
#pragma unroll
    for (int u = 0; u < 8; u++) {
        int idx = u * 256 + tid;
        int r = idx >> 5, c4 = idx & 31;
        *(float4*)&d_theta[((size_t)b * NQ_ + nbase + r) * CI_ + c4 * 4] =
            *(float4*)&st[r * 132 + c4 * 4];
    }
}

// ---------------------------------------------------------------------------
// Kernel B: g/phi conv1x1 + maxpool(1,2,2) -> d_val / d_key (b, m, ci)
// grid (T*HP = 128, B), 256 threads. Block covers one (t,hp) row pair:
// 64 contiguous full-res positions -> 16 pooled positions x 128 o.
// ---------------------------------------------------------------------------
__global__ void conv_gphi_kernel(const float* __restrict__ x,
                                 const float* __restrict__ gw, const float* __restrict__ gb,
                                 const float* __restrict__ pw, const float* __restrict__ pb) {
    extern __shared__ float sm[];
    float* xs  = sm;                 // [64][68]
    float* wsg = sm + 64 * 68;       // [128][68]
    float* wsp = wsg + 128 * 68;     // [128][68]
    const int b = blockIdx.y;
    const int t = blockIdx.x >> 4, hp = blockIdx.x & 15;
    const int nbase = t * 1024 + hp * 64;   // rows 2hp,2hp+1 are contiguous
    const int tid = threadIdx.x;
    const int ot = tid >> 3, jt = tid & 7;  // 32x4 o = 128 o ; 8x2 pooled cols = 16

    float ag[4][8], ap[4][8];
#pragma unroll
    for (int i = 0; i < 4; i++)
#pragma unroll
        for (int k = 0; k < 8; k++) { ag[i][k] = 0.f; ap[i][k] = 0.f; }

    for (int c0 = 0; c0 < C_; c0 += 64) {
        __syncthreads();
#pragma unroll
        for (int u = 0; u < 4; u++) {
            int idx = u * 256 + tid;
            int cc = idx >> 4, j4 = idx & 15;
            *(float4*)&xs[cc * 68 + j4 * 4] =
                *(const float4*)&x[((size_t)b * C_ + c0 + cc) * NQ_ + nbase + j4 * 4];
        }
#pragma unroll
        for (int u = 0; u < 8; u++) {
            int idx = u * 256 + tid;
            int oo = idx >> 4, c4 = idx & 15;
            *(float4*)&wsg[oo * 68 + c4 * 4] = *(const float4*)&gw[oo * C_ + c0 + c4 * 4];
            *(float4*)&wsp[oo * 68 + c4 * 4] = *(const float4*)&pw[oo * C_ + c0 + c4 * 4];
        }
        __syncthreads();
#pragma unroll 2
        for (int cc = 0; cc < 64; cc++) {
            float xv[8];
#pragma unroll
            for (int k2 = 0; k2 < 4; k2++) {
                xv[k2]     = xs[cc * 68 + 4 * jt + k2];        // row 2hp
                xv[4 + k2] = xs[cc * 68 + 32 + 4 * jt + k2];   // row 2hp+1
            }
#pragma unroll
            for (int i = 0; i < 4; i++) {
                float wgv = wsg[(ot * 4 + i) * 68 + cc];
                float wpv = wsp[(ot * 4 + i) * 68 + cc];
#pragma unroll
                for (int a = 0; a < 8; a++) {
                    ag[i][a] += wgv * xv[a];
                    ap[i][a] += wpv * xv[a];
                }
            }
        }
    }
    // pool 2x2 + stage for coalesced write
    __syncthreads();
    float* sv = sm;               // [16][132]
    float* sk = sm + 16 * 132;    // [16][132]
#pragma unroll
    for (int i = 0; i < 4; i++) {
        int o = ot * 4 + i;
        float bg = gb[o], bp = pb[o];
#pragma unroll
        for (int s2 = 0; s2 < 2; s2++) {
            float vg = fmaxf(fmaxf(ag[i][2 * s2], ag[i][2 * s2 + 1]),
                             fmaxf(ag[i][4 + 2 * s2], ag[i][5 + 2 * s2])) + bg;
            float vp = fmaxf(fmaxf(ap[i][2 * s2], ap[i][2 * s2 + 1]),
                             fmaxf(ap[i][4 + 2 * s2], ap[i][5 + 2 * s2])) + bp;
            int wp_ = 2 * jt + s2;
            sv[wp_ * 132 + o] = vg;
            sk[wp_ * 132 + o] = vp;
        }
    }
    __syncthreads();
    int mb = t * 256 + hp * 16;
#pragma unroll
    for (int u = 0; u < 2; u++) {
        int idx = u * 256 + tid;
        int mm = idx >> 5, c4 = idx & 31;
        *(float4*)&d_key[((size_t)b * NKV_ + mb + mm) * CI_ + c4 * 4] =
            *(float4*)&sk[mm * 132 + c4 * 4];
        *(float4*)&d_val[((size_t)b * NKV_ + mb + mm) * CI_ + c4 * 4] =
            *(float4*)&sv[mm * 132 + c4 * 4];
    }
}

// ---------------------------------------------------------------------------
// Kernel C: flash attention. grid (NQ/64, B), 256 threads.
// BQ=64, BK=64, d=128. Online softmax; output -> d_yy (b, ci, n) transposed.
// ---------------------------------------------------------------------------
__global__ void attn_kernel() {
    extern __shared__ float sm[];
    float* qs  = sm;                       // [64][132]
    float* kst = sm + 64 * 132;            // [128][68]  (K transposed: [k][m])
    float* vs  = kst + 128 * 68;           // [64][132]
    float* ps  = vs + 64 * 132;            // [64][66]
    const int b = blockIdx.y;
    const int qbase = blockIdx.x * 64;
    const int tid = threadIdx.x;
    const int ty = tid >> 4, tx = tid & 15;  // 16x4 q rows = 64 ; 16x4 kv cols = 64

#pragma unroll
    for (int u = 0; u < 8; u++) {
        int idx = u * 256 + tid;
        int r = idx >> 5, c4 = idx & 31;
        *(float4*)&qs[r * 132 + c4 * 4] =
            *(const float4*)&d_theta[((size_t)b * NQ_ + qbase + r) * CI_ + c4 * 4];
    }

    float mrow[4], lrow[4], o[4][8];
#pragma unroll
    for (int i = 0; i < 4; i++) {
        mrow[i] = -3.0e38f; lrow[i] = 0.f;
#pragma unroll
        for (int k = 0; k < 8; k++) o[i][k] = 0.f;
    }

    for (int mt = 0; mt < NKV_ / 64; mt++) {
        const int mbase = mt * 64;
        __syncthreads();
#pragma unroll
        for (int u = 0; u < 8; u++) {
            int idx = u * 256 + tid;
            int mm = idx >> 5, c4 = idx & 31;
            float4 kv = *(const float4*)&d_key[((size_t)b * NKV_ + mbase + mm) * CI_ + c4 * 4];
            kst[(c4 * 4 + 0) * 68 + mm] = kv.x;
            kst[(c4 * 4 + 1) * 68 + mm] = kv.y;
            kst[(c4 * 4 + 2) * 68 + mm] = kv.z;
            kst[(c4 * 4 + 3) * 68 + mm] = kv.w;
            *(float4*)&vs[mm * 132 + c4 * 4] =
                *(const float4*)&d_val[((size_t)b * NKV_ + mbase + mm) * CI_ + c4 * 4];
        }
        __syncthreads();

        float s[4][4];
#pragma unroll
        for (int i = 0; i < 4; i++)
#pragma unroll
            for (int j = 0; j < 4; j++) s[i][j] = 0.f;

#pragma unroll 4
        for (int k = 0; k < 128; k++) {
            float4 kk = *(float4*)&kst[k * 68 + tx * 4];
            float q0 = qs[(ty * 4 + 0) * 132 + k];
            float q1 = qs[(ty * 4 + 1) * 132 + k];
            float q2 = qs[(ty * 4 + 2) * 132 + k];
            float q3 = qs[(ty * 4 + 3) * 132 + k];
            s[0][0] += q0 * kk.x; s[0][1] += q0 * kk.y; s[0][2] += q0 * kk.z; s[0][3] += q0 * kk.w;
            s[1][0] += q1 * kk.x; s[1][1] += q1 * kk.y; s[1][2] += q1 * kk.z; s[1][3] += q1 * kk.w;
            s[2][0] += q2 * kk.x; s[2][1] += q2 * kk.y; s[2][2] += q2 * kk.z; s[2][3] += q2 * kk.w;
            s[3][0] += q3 * kk.x; s[3][1] += q3 * kk.y; s[3][2] += q3 * kk.z; s[3][3] += q3 * kk.w;
        }

#pragma unroll
        for (int i = 0; i < 4; i++) {
            float tm = fmaxf(fmaxf(s[i][0], s[i][1]), fmaxf(s[i][2], s[i][3]));
#pragma unroll
            for (int off = 8; off; off >>= 1)
                tm = fmaxf(tm, __shfl_xor_sync(0xffffffffu, tm, off));
            float nm = fmaxf(mrow[i], tm);
            float fac = __expf(mrow[i] - nm);
            float ts = 0.f;
#pragma unroll
            for (int j = 0; j < 4; j++) { s[i][j] = __expf(s[i][j] - nm); ts += s[i][j]; }
#pragma unroll
            for (int off = 8; off; off >>= 1)
                ts += __shfl_xor_sync(0xffffffffu, ts, off);
            lrow[i] = lrow[i] * fac + ts;
            mrow[i] = nm;
#pragma unroll
            for (int k = 0; k < 8; k++) o[i][k] *= fac;
#pragma unroll
            for (int j = 0; j < 4; j++) ps[(ty * 4 + i) * 66 + tx * 4 + j] = s[i][j];
        }
        __syncthreads();

#pragma unroll 2
        for (int mm = 0; mm < 64; mm++) {
            float4 v0 = *(float4*)&vs[mm * 132 + tx * 8];
            float4 v1 = *(float4*)&vs[mm * 132 + tx * 8 + 4];
            float p0 = ps[(ty * 4 + 0) * 66 + mm];
            float p1 = ps[(ty * 4 + 1) * 66 + mm];
            float p2 = ps[(ty * 4 + 2) * 66 + mm];
            float p3 = ps[(ty * 4 + 3) * 66 + mm];
            o[0][0] += p0 * v0.x; o[0][1] += p0 * v0.y; o[0][2] += p0 * v0.z; o[0][3] += p0 * v0.w;
            o[0][4] += p0 * v1.x; o[0][5] += p0 * v1.y; o[0][6] += p0 * v1.z; o[0][7] += p0 * v1.w;
            o[1][0] += p1 * v0.x; o[1][1] += p1 * v0.y; o[1][2] += p1 * v0.z; o[1][3] += p1 * v0.w;
            o[1][4] += p1 * v1.x; o[1][5] += p1 * v1.y; o[1][6] += p1 * v1.z; o[1][7] += p1 * v1.w;
            o[2][0] += p2 * v0.x; o[2][1] += p2 * v0.y; o[2][2] += p2 * v0.z; o[2][3] += p2 * v0.w;
            o[2][4] += p2 * v1.x; o[2][5] += p2 * v1.y; o[2][6] += p2 * v1.z; o[2][7] += p2 * v1.w;
            o[3][0] += p3 * v0.x; o[3][1] += p3 * v0.y; o[3][2] += p3 * v0.z; o[3][3] += p3 * v0.w;
            o[3][4] += p3 * v1.x; o[3][5] += p3 * v1.y; o[3][6] += p3 * v1.z; o[3][7] += p3 * v1.w;
        }
    }

    // finalize: normalize, transpose via smem, write d_yy (ci-major)
    __syncthreads();
#pragma unroll
    for (int i = 0; i < 4; i++) {
        float inv = 1.f / lrow[i];
#pragma unroll
        for (int k = 0; k < 8; k++)
            kst[(tx * 8 + k) * 68 + ty * 4 + i] = o[i][k] * inv;
    }
    __syncthreads();
#pragma unroll
    for (int u = 0; u < 8; u++) {
        int idx = u * 256 + tid;
        int crow = idx >> 4, r4 = idx & 15;
        *(float4*)&d_yy[((size_t)b * CI_ + crow) * NQ_ + qbase + r4 * 4] =
            *(float4*)&kst[crow * 68 + r4 * 4];
    }
}

// ---------------------------------------------------------------------------
// Kernel D: out = scale*(w_w @ yy + w_b) + shift + x
// grid (NQ/128, C/64, B), 256 threads. Tile 64 co x 128 n, full ci=128.
// FIXED: thread mapping is 16x16 (4 co x 8 n per thread).
// ---------------------------------------------------------------------------
__global__ void wconv_kernel(const float* __restrict__ x,
                             const float* __restrict__ ww, const float* __restrict__ wb,
                             const float* __restrict__ bng, const float* __restrict__ bnb,
                             const float* __restrict__ bnm, const float* __restrict__ bnv,
                             float* __restrict__ out) {
    extern __shared__ float sm[];
    float* ws = sm;              // [64][132]
    float* ys = sm + 64 * 132;   // [128][132]
    const int b = blockIdx.z;
    const int cobase = blockIdx.y * 64;
    const int nbase = blockIdx.x * 128;
    const int tid = threadIdx.x;
    const int ot = tid >> 4;     // 0..15 -> 4 co each (64 co)
    const int nt = tid & 15;     // 0..15 -> 8 n each (128 n)

#pragma unroll
    for (int u = 0; u < 8; u++) {
        int idx = u * 256 + tid;
        int co = idx >> 5, c4 = idx & 31;
        *(float4*)&ws[co * 132 + c4 * 4] =
            *(const float4*)&ww[(cobase + co) * CI_ + c4 * 4];
    }
#pragma unroll
    for (int u = 0; u < 16; u++) {
        int idx = u * 256 + tid;
        int ci = idx >> 5, n4 = idx & 31;
        *(float4*)&ys[ci * 132 + n4 * 4] =
            *(const float4*)&d_yy[((size_t)b * CI_ + ci) * NQ_ + nbase + n4 * 4];
    }
    __syncthreads();

    float acc[4][8];
#pragma unroll
    for (int i = 0; i < 4; i++)
#pragma unroll
        for (int k = 0; k < 8; k++) acc[i][k] = 0.f;

#pragma unroll 4
    for (int ci = 0; ci < 128; ci++) {
        float wv[4];
#pragma unroll
        for (int i = 0; i < 4; i++) wv[i] = ws[(ot * 4 + i) * 132 + ci];
        float4 y0 = *(float4*)&ys[ci * 132 + nt * 8];
        float4 y1 = *(float4*)&ys[ci * 132 + nt * 8 + 4];
        float yv[8] = {y0.x, y0.y, y0.z, y0.w, y1.x, y1.y, y1.z, y1.w};
#pragma unroll
        for (int i = 0; i < 4; i++)
#pragma unroll
            for (int k = 0; k < 8; k++) acc[i][k] += wv[i] * yv[k];
    }

#pragma unroll
    for (int i = 0; i < 4; i++) {
        int co = cobase + ot * 4 + i;
        float sc = bng[co] * rsqrtf(bnv[co] + 1e-5f);
        float sh = bnb[co] - bnm[co] * sc + sc * wb[co];
        size_t base = ((size_t)b * C_ + co) * NQ_ + nbase + nt * 8;
#pragma unroll
        for (int k = 0; k < 8; k++)
            out[base + k] = acc[i][k] * sc + sh + x[base + k];
    }
}

// ---------------------------------------------------------------------------
extern "C" void kernel_launch(void* const* d_in, const int* in_sizes, int n_in,
                              void* d_out, int out_size) {
    const float* x    = (const float*)d_in[0];
    const float* g_w  = (const float*)d_in[1];
    const float* g_b  = (const float*)d_in[2];
    const float* th_w = (const float*)d_in[3];
    const float* th_b = (const float*)d_in[4];
    const float* ph_w = (const float*)d_in[5];
    const float* ph_b = (const float*)d_in[6];
    const float* w_w  = (const float*)d_in[7];
    const float* w_b  = (const float*)d_in[8];
    const float* bn_g = (const float*)d_in[9];
    const float* bn_b = (const float*)d_in[10];
    const float* bn_m = (const float*)d_in[11];
    const float* bn_v = (const float*)d_in[12];
    float* out = (float*)d_out;

    const int smA = (64 * 68 + 128 * 68) * 4;                         // 52224
    const int smB = (64 * 68 + 2 * 128 * 68) * 4;                     // 87040
    const int smC = (64 * 132 + 128 * 68 + 64 * 132 + 64 * 66) * 4;   // 119296
    const int smD = (64 * 132 + 128 * 132) * 4;                       // 101376

    cudaFuncSetAttribute(conv_theta_kernel, cudaFuncAttributeMaxDynamicSharedMemorySize, smA);
    cudaFuncSetAttribute(conv_gphi_kernel,  cudaFuncAttributeMaxDynamicSharedMemorySize, smB);
    cudaFuncSetAttribute(attn_kernel,       cudaFuncAttributeMaxDynamicSharedMemorySize, smC);
    cudaFuncSetAttribute(wconv_kernel,      cudaFuncAttributeMaxDynamicSharedMemorySize, smD);

    conv_theta_kernel<<<dim3(NQ_ / 64, B_), 256, smA>>>(x, th_w, th_b);
    conv_gphi_kernel<<<dim3(128, B_), 256, smB>>>(x, g_w, g_b, ph_w, ph_b);
    attn_kernel<<<dim3(NQ_ / 64, B_), 256, smC>>>();
    wconv_kernel<<<dim3(NQ_ / 128, C_ / 64, B_), 256, smD>>>(x, w_w, w_b,
                                                             bn_g, bn_b, bn_m, bn_v, out);
}

// round 3
// speedup vs baseline: 2.4315x; 2.4315x over previous
#include <cuda_runtime.h>
#include <math.h>
#include <stdint.h>

#define B_  4
#define C_  256
#define CI_ 128
#define NQ_ 8192
#define NKV_ 2048

// scratch (no cudaMalloc allowed)
__device__ float d_theta[(size_t)B_ * NQ_ * CI_];   // (b, n, ci)
__device__ float d_key  [(size_t)B_ * NKV_ * CI_];  // (b, m, ci)  pooled phi
__device__ float d_val  [(size_t)B_ * NKV_ * CI_];  // (b, m, ci)  pooled g
__device__ float d_yy   [(size_t)B_ * CI_ * NQ_];   // (b, ci, n)

__device__ __forceinline__ float f2tf(float f) {
    uint32_t u;
    asm("cvt.rna.tf32.f32 %0, %1;" : "=r"(u) : "f"(f));
    return __uint_as_float(u);
}

__device__ __forceinline__ void mma_tf32(float* c, const uint32_t* a, const uint32_t* b) {
    asm volatile(
        "mma.sync.aligned.m16n8k8.row.col.f32.tf32.tf32.f32 "
        "{%0,%1,%2,%3}, {%4,%5,%6,%7}, {%8,%9}, {%0,%1,%2,%3};"
        : "+f"(c[0]), "+f"(c[1]), "+f"(c[2]), "+f"(c[3])
        : "r"(a[0]), "r"(a[1]), "r"(a[2]), "r"(a[3]), "r"(b[0]), "r"(b[1]));
}

// ---------------------------------------------------------------------------
// Kernel A: theta = conv1x1(x, theta_w) + theta_b  -> d_theta (b, n, ci)
// ---------------------------------------------------------------------------
__global__ void conv_theta_kernel(const float* __restrict__ x,
                                  const float* __restrict__ tw,
                                  const float* __restrict__ tb) {
    extern __shared__ float sm[];
    float* xs = sm;              // [64][68]
    float* ws = sm + 64 * 68;    // [128][68]
    const int b = blockIdx.y;
    const int nbase = blockIdx.x * 64;
    const int tid = threadIdx.x;
    const int ot = tid >> 3;
    const int nt = tid & 7;

    float acc[4][8];
#pragma unroll
    for (int i = 0; i < 4; i++)
#pragma unroll
        for (int k = 0; k < 8; k++) acc[i][k] = 0.f;

    for (int c0 = 0; c0 < C_; c0 += 64) {
        __syncthreads();
#pragma unroll
        for (int u = 0; u < 4; u++) {
            int idx = u * 256 + tid;
            int cc = idx >> 4, j4 = idx & 15;
            *(float4*)&xs[cc * 68 + j4 * 4] =
                *(const float4*)&x[((size_t)b * C_ + c0 + cc) * NQ_ + nbase + j4 * 4];
        }
#pragma unroll
        for (int u = 0; u < 8; u++) {
            int idx = u * 256 + tid;
            int oo = idx >> 4, c4 = idx & 15;
            *(float4*)&ws[oo * 68 + c4 * 4] =
                *(const float4*)&tw[oo * C_ + c0 + c4 * 4];
        }
        __syncthreads();
#pragma unroll 4
        for (int cc = 0; cc < 64; cc++) {
            float wv[4];
#pragma unroll
            for (int i = 0; i < 4; i++) wv[i] = ws[(ot * 4 + i) * 68 + cc];
            float4 xa = *(float4*)&xs[cc * 68 + nt * 8];
            float4 xb = *(float4*)&xs[cc * 68 + nt * 8 + 4];
            float xv[8] = {xa.x, xa.y, xa.z, xa.w, xb.x, xb.y, xb.z, xb.w};
#pragma unroll
            for (int i = 0; i < 4; i++)
#pragma unroll
                for (int k = 0; k < 8; k++) acc[i][k] += wv[i] * xv[k];
        }
    }
    __syncthreads();
    float* st = sm;  // [64][132]
#pragma unroll
    for (int i = 0; i < 4; i++) {
        float bias = tb[ot * 4 + i];
#pragma unroll
        for (int k = 0; k < 8; k++)
            st[(nt * 8 + k) * 132 + ot * 4 + i] = acc[i][k] + bias;
    }
    __syncthreads();
#pragma unroll
    for (int u = 0; u < 8; u++) {
        int idx = u * 256 + tid;
        int r = idx >> 5, c4 = idx & 31;
        *(float4*)&d_theta[((size_t)b * NQ_ + nbase + r) * CI_ + c4 * 4] =
            *(float4*)&st[r * 132 + c4 * 4];
    }
}

// ---------------------------------------------------------------------------
// Kernel B: g/phi conv1x1 + maxpool(1,2,2) -> d_val / d_key (b, m, ci)
// ---------------------------------------------------------------------------
__global__ void conv_gphi_kernel(const float* __restrict__ x,
                                 const float* __restrict__ gw, const float* __restrict__ gb,
                                 const float* __restrict__ pw, const float* __restrict__ pb) {
    extern __shared__ float sm[];
    float* xs  = sm;                 // [64][68]
    float* wsg = sm + 64 * 68;       // [128][68]
    float* wsp = wsg + 128 * 68;     // [128][68]
    const int b = blockIdx.y;
    const int t = blockIdx.x >> 4, hp = blockIdx.x & 15;
    const int nbase = t * 1024 + hp * 64;
    const int tid = threadIdx.x;
    const int ot = tid >> 3, jt = tid & 7;

    float ag[4][8], ap[4][8];
#pragma unroll
    for (int i = 0; i < 4; i++)
#pragma unroll
        for (int k = 0; k < 8; k++) { ag[i][k] = 0.f; ap[i][k] = 0.f; }

    for (int c0 = 0; c0 < C_; c0 += 64) {
        __syncthreads();
#pragma unroll
        for (int u = 0; u < 4; u++) {
            int idx = u * 256 + tid;
            int cc = idx >> 4, j4 = idx & 15;
            *(float4*)&xs[cc * 68 + j4 * 4] =
                *(const float4*)&x[((size_t)b * C_ + c0 + cc) * NQ_ + nbase + j4 * 4];
        }
#pragma unroll
        for (int u = 0; u < 8; u++) {
            int idx = u * 256 + tid;
            int oo = idx >> 4, c4 = idx & 15;
            *(float4*)&wsg[oo * 68 + c4 * 4] = *(const float4*)&gw[oo * C_ + c0 + c4 * 4];
            *(float4*)&wsp[oo * 68 + c4 * 4] = *(const float4*)&pw[oo * C_ + c0 + c4 * 4];
        }
        __syncthreads();
#pragma unroll 2
        for (int cc = 0; cc < 64; cc++) {
            float xv[8];
#pragma unroll
            for (int k2 = 0; k2 < 4; k2++) {
                xv[k2]     = xs[cc * 68 + 4 * jt + k2];
                xv[4 + k2] = xs[cc * 68 + 32 + 4 * jt + k2];
            }
#pragma unroll
            for (int i = 0; i < 4; i++) {
                float wgv = wsg[(ot * 4 + i) * 68 + cc];
                float wpv = wsp[(ot * 4 + i) * 68 + cc];
#pragma unroll
                for (int a = 0; a < 8; a++) {
                    ag[i][a] += wgv * xv[a];
                    ap[i][a] += wpv * xv[a];
                }
            }
        }
    }
    __syncthreads();
    float* sv = sm;               // [16][132]
    float* sk = sm + 16 * 132;    // [16][132]
#pragma unroll
    for (int i = 0; i < 4; i++) {
        int o = ot * 4 + i;
        float bg = gb[o], bp = pb[o];
#pragma unroll
        for (int s2 = 0; s2 < 2; s2++) {
            float vg = fmaxf(fmaxf(ag[i][2 * s2], ag[i][2 * s2 + 1]),
                             fmaxf(ag[i][4 + 2 * s2], ag[i][5 + 2 * s2])) + bg;
            float vp = fmaxf(fmaxf(ap[i][2 * s2], ap[i][2 * s2 + 1]),
                             fmaxf(ap[i][4 + 2 * s2], ap[i][5 + 2 * s2])) + bp;
            int wp_ = 2 * jt + s2;
            sv[wp_ * 132 + o] = vg;
            sk[wp_ * 132 + o] = vp;
        }
    }
    __syncthreads();
    int mb = t * 256 + hp * 16;
#pragma unroll
    for (int u = 0; u < 2; u++) {
        int idx = u * 256 + tid;
        int mm = idx >> 5, c4 = idx & 31;
        *(float4*)&d_key[((size_t)b * NKV_ + mb + mm) * CI_ + c4 * 4] =
            *(float4*)&sk[mm * 132 + c4 * 4];
        *(float4*)&d_val[((size_t)b * NKV_ + mb + mm) * CI_ + c4 * 4] =
            *(float4*)&sv[mm * 132 + c4 * 4];
    }
}

// ---------------------------------------------------------------------------
// Kernel C: flash attention with tf32 mma.sync. grid (NQ/128, B), 256 thr.
// BQ=128, BK=64, d=128. 8 warps; warp w owns q rows [16w, 16w+16).
// ---------------------------------------------------------------------------
__global__ void __launch_bounds__(256, 1) attn_kernel() {
    extern __shared__ float sm[];
    float* Qs  = sm;                     // [128][132] tf32
    float* Ks  = Qs + 128 * 132;         // [64][132]  tf32, row-major (kv, ci)
    float* VTs = Ks + 64 * 132;          // [128][68]  tf32, (ci, kv)
    float* Ps  = VTs + 128 * 68;         // [128][68]  tf32, (q, kv)
    const int b = blockIdx.y;
    const int qbase = blockIdx.x * 128;
    const int tid = threadIdx.x;
    const int warp = tid >> 5;
    const int lane = tid & 31;
    const int g = lane >> 2;       // group row
    const int q4 = lane & 3;       // thread-in-group
    const int r0 = warp * 16 + g;  // warp's q row (local)

    // stage Q (once), convert to tf32
#pragma unroll
    for (int u = 0; u < 16; u++) {
        int idx = u * 256 + tid;
        int r = idx >> 5, c4 = idx & 31;
        float4 v = *(const float4*)&d_theta[((size_t)b * NQ_ + qbase + r) * CI_ + c4 * 4];
        v.x = f2tf(v.x); v.y = f2tf(v.y); v.z = f2tf(v.z); v.w = f2tf(v.w);
        *(float4*)&Qs[r * 132 + c4 * 4] = v;
    }

    float m[2] = {-3.0e38f, -3.0e38f}, l[2] = {0.f, 0.f};
    float oacc[16][4];
#pragma unroll
    for (int i = 0; i < 16; i++)
#pragma unroll
        for (int j = 0; j < 4; j++) oacc[i][j] = 0.f;

    for (int mt = 0; mt < NKV_ / 64; mt++) {
        const int mbase = mt * 64;
        __syncthreads();
        // stage K (row-major) and V^T, convert to tf32
#pragma unroll
        for (int u = 0; u < 8; u++) {
            int idx = u * 256 + tid;
            int mm = idx >> 5, c4 = idx & 31;
            float4 kv = *(const float4*)&d_key[((size_t)b * NKV_ + mbase + mm) * CI_ + c4 * 4];
            kv.x = f2tf(kv.x); kv.y = f2tf(kv.y); kv.z = f2tf(kv.z); kv.w = f2tf(kv.w);
            *(float4*)&Ks[mm * 132 + c4 * 4] = kv;
            float4 vv = *(const float4*)&d_val[((size_t)b * NKV_ + mbase + mm) * CI_ + c4 * 4];
            VTs[(c4 * 4 + 0) * 68 + mm] = f2tf(vv.x);
            VTs[(c4 * 4 + 1) * 68 + mm] = f2tf(vv.y);
            VTs[(c4 * 4 + 2) * 68 + mm] = f2tf(vv.z);
            VTs[(c4 * 4 + 3) * 68 + mm] = f2tf(vv.w);
        }
        __syncthreads();

        // S = Q K^T : 8 n-tiles of 8 cols, 16 k-steps
        float sacc[8][4];
#pragma unroll
        for (int i = 0; i < 8; i++)
#pragma unroll
            for (int j = 0; j < 4; j++) sacc[i][j] = 0.f;

#pragma unroll
        for (int ks = 0; ks < 16; ks++) {
            uint32_t a[4];
            int c0 = ks * 8 + q4;
            a[0] = __float_as_uint(Qs[r0 * 132 + c0]);
            a[1] = __float_as_uint(Qs[(r0 + 8) * 132 + c0]);
            a[2] = __float_as_uint(Qs[r0 * 132 + c0 + 4]);
            a[3] = __float_as_uint(Qs[(r0 + 8) * 132 + c0 + 4]);
#pragma unroll
            for (int nt = 0; nt < 8; nt++) {
                uint32_t bb[2];
                int n = nt * 8 + g;
                bb[0] = __float_as_uint(Ks[n * 132 + c0]);
                bb[1] = __float_as_uint(Ks[n * 132 + c0 + 4]);
                mma_tf32(sacc[nt], a, bb);
            }
        }

        // online softmax, rows r0 (h=0) and r0+8 (h=1)
#pragma unroll
        for (int h = 0; h < 2; h++) {
            float tmax = -3.0e38f;
#pragma unroll
            for (int nt = 0; nt < 8; nt++)
                tmax = fmaxf(tmax, fmaxf(sacc[nt][2 * h], sacc[nt][2 * h + 1]));
            tmax = fmaxf(tmax, __shfl_xor_sync(0xffffffffu, tmax, 1));
            tmax = fmaxf(tmax, __shfl_xor_sync(0xffffffffu, tmax, 2));
            float nm = fmaxf(m[h], tmax);
            float fac = __expf(m[h] - nm);
            float s = 0.f;
#pragma unroll
            for (int nt = 0; nt < 8; nt++) {
                float e0 = __expf(sacc[nt][2 * h]     - nm);
                float e1 = __expf(sacc[nt][2 * h + 1] - nm);
                sacc[nt][2 * h] = e0; sacc[nt][2 * h + 1] = e1;
                s += e0 + e1;
            }
            s += __shfl_xor_sync(0xffffffffu, s, 1);
            s += __shfl_xor_sync(0xffffffffu, s, 2);
            l[h] = l[h] * fac + s;
            m[h] = nm;
#pragma unroll
            for (int ot = 0; ot < 16; ot++) {
                oacc[ot][2 * h]     *= fac;
                oacc[ot][2 * h + 1] *= fac;
            }
        }

        // store P (per-warp rows, no cross-warp dependency)
#pragma unroll
        for (int nt = 0; nt < 8; nt++) {
            int cb = nt * 8 + 2 * q4;
            Ps[r0 * 68 + cb]           = f2tf(sacc[nt][0]);
            Ps[r0 * 68 + cb + 1]       = f2tf(sacc[nt][1]);
            Ps[(r0 + 8) * 68 + cb]     = f2tf(sacc[nt][2]);
            Ps[(r0 + 8) * 68 + cb + 1] = f2tf(sacc[nt][3]);
        }
        __syncwarp();

        // O += P V : k=64 (8 k-steps), n=128 (16 n-tiles)
#pragma unroll
        for (int ks = 0; ks < 8; ks++) {
            uint32_t a[4];
            int kk = ks * 8 + q4;
            a[0] = __float_as_uint(Ps[r0 * 68 + kk]);
            a[1] = __float_as_uint(Ps[(r0 + 8) * 68 + kk]);
            a[2] = __float_as_uint(Ps[r0 * 68 + kk + 4]);
            a[3] = __float_as_uint(Ps[(r0 + 8) * 68 + kk + 4]);
#pragma unroll
            for (int nt = 0; nt < 16; nt++) {
                uint32_t bb[2];
                int n = nt * 8 + g;
                bb[0] = __float_as_uint(VTs[n * 68 + kk]);
                bb[1] = __float_as_uint(VTs[n * 68 + kk + 4]);
                mma_tf32(oacc[nt], a, bb);
            }
        }
    }

    // epilogue: normalize, transpose via smem (reuse Qs as [128 ci][132]),
    // write d_yy (b, ci, n)
    __syncthreads();
    float inv0 = 1.f / l[0], inv1 = 1.f / l[1];
#pragma unroll
    for (int nt = 0; nt < 16; nt++) {
        int ci = nt * 8 + 2 * q4;
        Qs[ci * 132 + r0]           = oacc[nt][0] * inv0;
        Qs[(ci + 1) * 132 + r0]     = oacc[nt][1] * inv0;
        Qs[ci * 132 + r0 + 8]       = oacc[nt][2] * inv1;
        Qs[(ci + 1) * 132 + r0 + 8] = oacc[nt][3] * inv1;
    }
    __syncthreads();
#pragma unroll
    for (int u = 0; u < 16; u++) {
        int idx = u * 256 + tid;
        int crow = idx >> 5, c4 = idx & 31;
        *(float4*)&d_yy[((size_t)b * CI_ + crow) * NQ_ + qbase + c4 * 4] =
            *(float4*)&Qs[crow * 132 + c4 * 4];
    }
}

// ---------------------------------------------------------------------------
// Kernel D: out = scale*(w_w @ yy + w_b) + shift + x
// ---------------------------------------------------------------------------
__global__ void wconv_kernel(const float* __restrict__ x,
                             const float* __restrict__ ww, const float* __restrict__ wb,
                             const float* __restrict__ bng, const float* __restrict__ bnb,
                             const float* __restrict__ bnm, const float* __restrict__ bnv,
                             float* __restrict__ out) {
    extern __shared__ float sm[];
    float* ws = sm;              // [64][132]
    float* ys = sm + 64 * 132;   // [128][132]
    const int b = blockIdx.z;
    const int cobase = blockIdx.y * 64;
    const int nbase = blockIdx.x * 128;
    const int tid = threadIdx.x;
    const int ot = tid >> 4;
    const int nt = tid & 15;

#pragma unroll
    for (int u = 0; u < 8; u++) {
        int idx = u * 256 + tid;
        int co = idx >> 5, c4 = idx & 31;
        *(float4*)&ws[co * 132 + c4 * 4] =
            *(const float4*)&ww[(cobase + co) * CI_ + c4 * 4];
    }
#pragma unroll
    for (int u = 0; u < 16; u++) {
        int idx = u * 256 + tid;
        int ci = idx >> 5, n4 = idx & 31;
        *(float4*)&ys[ci * 132 + n4 * 4] =
            *(const float4*)&d_yy[((size_t)b * CI_ + ci) * NQ_ + nbase + n4 * 4];
    }
    __syncthreads();

    float acc[4][8];
#pragma unroll
    for (int i = 0; i < 4; i++)
#pragma unroll
        for (int k = 0; k < 8; k++) acc[i][k] = 0.f;

#pragma unroll 4
    for (int ci = 0; ci < 128; ci++) {
        float wv[4];
#pragma unroll
        for (int i = 0; i < 4; i++) wv[i] = ws[(ot * 4 + i) * 132 + ci];
        float4 y0 = *(float4*)&ys[ci * 132 + nt * 8];
        float4 y1 = *(float4*)&ys[ci * 132 + nt * 8 + 4];
        float yv[8] = {y0.x, y0.y, y0.z, y0.w, y1.x, y1.y, y1.z, y1.w};
#pragma unroll
        for (int i = 0; i < 4; i++)
#pragma unroll
            for (int k = 0; k < 8; k++) acc[i][k] += wv[i] * yv[k];
    }

#pragma unroll
    for (int i = 0; i < 4; i++) {
        int co = cobase + ot * 4 + i;
        float sc = bng[co] * rsqrtf(bnv[co] + 1e-5f);
        float sh = bnb[co] - bnm[co] * sc + sc * wb[co];
        size_t base = ((size_t)b * C_ + co) * NQ_ + nbase + nt * 8;
#pragma unroll
        for (int k = 0; k < 8; k++)
            out[base + k] = acc[i][k] * sc + sh + x[base + k];
    }
}

// ---------------------------------------------------------------------------
extern "C" void kernel_launch(void* const* d_in, const int* in_sizes, int n_in,
                              void* d_out, int out_size) {
    const float* x    = (const float*)d_in[0];
    const float* g_w  = (const float*)d_in[1];
    const float* g_b  = (const float*)d_in[2];
    const float* th_w = (const float*)d_in[3];
    const float* th_b = (const float*)d_in[4];
    const float* ph_w = (const float*)d_in[5];
    const float* ph_b = (const float*)d_in[6];
    const float* w_w  = (const float*)d_in[7];
    const float* w_b  = (const float*)d_in[8];
    const float* bn_g = (const float*)d_in[9];
    const float* bn_b = (const float*)d_in[10];
    const float* bn_m = (const float*)d_in[11];
    const float* bn_v = (const float*)d_in[12];
    float* out = (float*)d_out;

    const int smA = (64 * 68 + 128 * 68) * 4;                         // 52224
    const int smB = (64 * 68 + 2 * 128 * 68) * 4;                     // 87040
    const int smC = (128 * 132 + 64 * 132 + 128 * 68 + 128 * 68) * 4; // 171008
    const int smD = (64 * 132 + 128 * 132) * 4;                       // 101376

    cudaFuncSetAttribute(conv_theta_kernel, cudaFuncAttributeMaxDynamicSharedMemorySize, smA);
    cudaFuncSetAttribute(conv_gphi_kernel,  cudaFuncAttributeMaxDynamicSharedMemorySize, smB);
    cudaFuncSetAttribute(attn_kernel,       cudaFuncAttributeMaxDynamicSharedMemorySize, smC);
    cudaFuncSetAttribute(wconv_kernel,      cudaFuncAttributeMaxDynamicSharedMemorySize, smD);

    conv_theta_kernel<<<dim3(NQ_ / 64, B_), 256, smA>>>(x, th_w, th_b);
    conv_gphi_kernel<<<dim3(128, B_), 256, smB>>>(x, g_w, g_b, ph_w, ph_b);
    attn_kernel<<<dim3(NQ_ / 128, B_), 256, smC>>>();
    wconv_kernel<<<dim3(NQ_ / 128, C_ / 64, B_), 256, smD>>>(x, w_w, w_b,
                                                             bn_g, bn_b, bn_m, bn_v, out);
}

// round 4
// speedup vs baseline: 3.2657x; 1.3431x over previous
#include <cuda_runtime.h>
#include <math.h>
#include <stdint.h>

#define B_  4
#define C_  256
#define CI_ 128
#define NQ_ 8192
#define NKV_ 2048

// scratch (no cudaMalloc allowed)
__device__ float d_theta[(size_t)B_ * NQ_ * CI_];   // (b, n, ci)
__device__ float d_key  [(size_t)B_ * NKV_ * CI_];  // (b, m, ci)  pooled phi
__device__ float d_val  [(size_t)B_ * NKV_ * CI_];  // (b, m, ci)  pooled g
__device__ float d_yy   [(size_t)B_ * NQ_ * CI_];   // (b, n, ci)

__device__ __forceinline__ float f2tf(float f) {
    uint32_t u;
    asm("cvt.rna.tf32.f32 %0, %1;" : "=r"(u) : "f"(f));
    return __uint_as_float(u);
}

__device__ __forceinline__ void mma_tf32(float* c, const uint32_t* a, const uint32_t* b) {
    asm volatile(
        "mma.sync.aligned.m16n8k8.row.col.f32.tf32.tf32.f32 "
        "{%0,%1,%2,%3}, {%4,%5,%6,%7}, {%8,%9}, {%0,%1,%2,%3};"
        : "+f"(c[0]), "+f"(c[1]), "+f"(c[2]), "+f"(c[3])
        : "r"(a[0]), "r"(a[1]), "r"(a[2]), "r"(a[3]), "r"(b[0]), "r"(b[1]));
}

// ---------------------------------------------------------------------------
// Kernel A: theta = conv1x1(x, theta_w) + theta_b -> d_theta (b, n, ci)
// GEMM: M=n(128/block), N=o(128), K=c(256, chunks of 64). tf32 MMA.
// grid (NQ/128, B), 256 threads (8 warps, 2 M x 4 N).
// ---------------------------------------------------------------------------
__global__ void __launch_bounds__(256) conv_theta_kernel(
        const float* __restrict__ x,
        const float* __restrict__ tw,
        const float* __restrict__ tb) {
    extern __shared__ float sm[];
    float* Xs = sm;              // [128 n][68]  (n, c) tf32
    float* Ws = sm + 128 * 68;   // [128 o][68]  (o, c) tf32
    const int b = blockIdx.y;
    const int nbase = blockIdx.x * 128;
    const int tid = threadIdx.x;
    const int warp = tid >> 5, lane = tid & 31;
    const int g = lane >> 2, q4 = lane & 3;
    const int m0 = (warp >> 2) * 64;   // n offset of warp
    const int n0 = (warp & 3) * 32;    // o offset of warp

    float acc[4][4][4];
#pragma unroll
    for (int i = 0; i < 4; i++)
#pragma unroll
        for (int j = 0; j < 4; j++)
#pragma unroll
            for (int k = 0; k < 4; k++) acc[i][j][k] = 0.f;

    for (int c0 = 0; c0 < C_; c0 += 64) {
        __syncthreads();
        // X: 64 c rows x 128 n, stored transposed (n, c)
#pragma unroll
        for (int u = 0; u < 8; u++) {
            int idx = u * 256 + tid;
            int cc = idx >> 5, j4 = idx & 31;
            float4 v = *(const float4*)&x[((size_t)b * C_ + c0 + cc) * NQ_ + nbase + j4 * 4];
            Xs[(j4 * 4 + 0) * 68 + cc] = f2tf(v.x);
            Xs[(j4 * 4 + 1) * 68 + cc] = f2tf(v.y);
            Xs[(j4 * 4 + 2) * 68 + cc] = f2tf(v.z);
            Xs[(j4 * 4 + 3) * 68 + cc] = f2tf(v.w);
        }
        // W: 128 o x 64 c
#pragma unroll
        for (int u = 0; u < 8; u++) {
            int idx = u * 256 + tid;
            int oo = idx >> 4, c4 = idx & 15;
            float4 w = *(const float4*)&tw[oo * C_ + c0 + c4 * 4];
            w.x = f2tf(w.x); w.y = f2tf(w.y); w.z = f2tf(w.z); w.w = f2tf(w.w);
            *(float4*)&Ws[oo * 68 + c4 * 4] = w;
        }
        __syncthreads();
#pragma unroll
        for (int ks = 0; ks < 8; ks++) {
            int k = ks * 8;
            uint32_t a[4][4];
#pragma unroll
            for (int mt = 0; mt < 4; mt++) {
                int r = m0 + mt * 16 + g;
                a[mt][0] = __float_as_uint(Xs[r * 68 + k + q4]);
                a[mt][1] = __float_as_uint(Xs[(r + 8) * 68 + k + q4]);
                a[mt][2] = __float_as_uint(Xs[r * 68 + k + q4 + 4]);
                a[mt][3] = __float_as_uint(Xs[(r + 8) * 68 + k + q4 + 4]);
            }
#pragma unroll
            for (int nt = 0; nt < 4; nt++) {
                uint32_t bb[2];
                int n = n0 + nt * 8 + g;
                bb[0] = __float_as_uint(Ws[n * 68 + k + q4]);
                bb[1] = __float_as_uint(Ws[n * 68 + k + q4 + 4]);
#pragma unroll
                for (int mt = 0; mt < 4; mt++) mma_tf32(acc[mt][nt], a[mt], bb);
            }
        }
    }
    // epilogue: + bias, write (n, ci)
#pragma unroll
    for (int nt = 0; nt < 4; nt++) {
        int o = n0 + nt * 8 + 2 * q4;
        float b0 = tb[o], b1 = tb[o + 1];
#pragma unroll
        for (int mt = 0; mt < 4; mt++) {
            size_t r = (size_t)b * NQ_ + nbase + m0 + mt * 16 + g;
            float2 v0 = {acc[mt][nt][0] + b0, acc[mt][nt][1] + b1};
            float2 v1 = {acc[mt][nt][2] + b0, acc[mt][nt][3] + b1};
            *(float2*)&d_theta[r * CI_ + o] = v0;
            *(float2*)&d_theta[(r + 8) * CI_ + o] = v1;
        }
    }
}

// ---------------------------------------------------------------------------
// Kernel B: g/phi conv1x1 + maxpool(1,2,2) -> d_val/d_key (b, m, ci)
// GEMM: M=n(64/block), N=o(128), K=c(256), two GEMMs sharing the X tile.
// grid (128, B), 256 threads (8 warps, 2 M x 4 N).
// ---------------------------------------------------------------------------
__global__ void __launch_bounds__(256) conv_gphi_kernel(
        const float* __restrict__ x,
        const float* __restrict__ gw, const float* __restrict__ gb,
        const float* __restrict__ pw, const float* __restrict__ pb) {
    extern __shared__ float sm[];
    float* Xs = sm;               // [64 n][68]
    float* Wg = sm + 64 * 68;     // [128 o][68]
    float* Wp = Wg + 128 * 68;    // [128 o][68]
    const int b = blockIdx.y;
    const int t = blockIdx.x >> 4, hp = blockIdx.x & 15;
    const int nbase = t * 1024 + hp * 64;
    const int tid = threadIdx.x;
    const int warp = tid >> 5, lane = tid & 31;
    const int g = lane >> 2, q4 = lane & 3;
    const int m0 = (warp >> 2) * 32;
    const int n0 = (warp & 3) * 32;

    float ag[2][4][4], ap[2][4][4];
#pragma unroll
    for (int i = 0; i < 2; i++)
#pragma unroll
        for (int j = 0; j < 4; j++)
#pragma unroll
            for (int k = 0; k < 4; k++) { ag[i][j][k] = 0.f; ap[i][j][k] = 0.f; }

    for (int c0 = 0; c0 < C_; c0 += 64) {
        __syncthreads();
#pragma unroll
        for (int u = 0; u < 4; u++) {
            int idx = u * 256 + tid;
            int cc = idx >> 4, j4 = idx & 15;
            float4 v = *(const float4*)&x[((size_t)b * C_ + c0 + cc) * NQ_ + nbase + j4 * 4];
            Xs[(j4 * 4 + 0) * 68 + cc] = f2tf(v.x);
            Xs[(j4 * 4 + 1) * 68 + cc] = f2tf(v.y);
            Xs[(j4 * 4 + 2) * 68 + cc] = f2tf(v.z);
            Xs[(j4 * 4 + 3) * 68 + cc] = f2tf(v.w);
        }
#pragma unroll
        for (int u = 0; u < 8; u++) {
            int idx = u * 256 + tid;
            int oo = idx >> 4, c4 = idx & 15;
            float4 w = *(const float4*)&gw[oo * C_ + c0 + c4 * 4];
            w.x = f2tf(w.x); w.y = f2tf(w.y); w.z = f2tf(w.z); w.w = f2tf(w.w);
            *(float4*)&Wg[oo * 68 + c4 * 4] = w;
            float4 p = *(const float4*)&pw[oo * C_ + c0 + c4 * 4];
            p.x = f2tf(p.x); p.y = f2tf(p.y); p.z = f2tf(p.z); p.w = f2tf(p.w);
            *(float4*)&Wp[oo * 68 + c4 * 4] = p;
        }
        __syncthreads();
#pragma unroll
        for (int ks = 0; ks < 8; ks++) {
            int k = ks * 8;
            uint32_t a[2][4];
#pragma unroll
            for (int mt = 0; mt < 2; mt++) {
                int r = m0 + mt * 16 + g;
                a[mt][0] = __float_as_uint(Xs[r * 68 + k + q4]);
                a[mt][1] = __float_as_uint(Xs[(r + 8) * 68 + k + q4]);
                a[mt][2] = __float_as_uint(Xs[r * 68 + k + q4 + 4]);
                a[mt][3] = __float_as_uint(Xs[(r + 8) * 68 + k + q4 + 4]);
            }
#pragma unroll
            for (int nt = 0; nt < 4; nt++) {
                int n = n0 + nt * 8 + g;
                uint32_t bg_[2], bp_[2];
                bg_[0] = __float_as_uint(Wg[n * 68 + k + q4]);
                bg_[1] = __float_as_uint(Wg[n * 68 + k + q4 + 4]);
                bp_[0] = __float_as_uint(Wp[n * 68 + k + q4]);
                bp_[1] = __float_as_uint(Wp[n * 68 + k + q4 + 4]);
#pragma unroll
                for (int mt = 0; mt < 2; mt++) {
                    mma_tf32(ag[mt][nt], a[mt], bg_);
                    mma_tf32(ap[mt][nt], a[mt], bp_);
                }
            }
        }
    }
    // stage S (64 x 128) for both, then pool
    __syncthreads();
    float* Sg = sm;                // [64][132]
    float* Sp = sm + 64 * 132;     // [64][132]
#pragma unroll
    for (int mt = 0; mt < 2; mt++) {
#pragma unroll
        for (int nt = 0; nt < 4; nt++) {
            int r = m0 + mt * 16 + g;
            int o = n0 + nt * 8 + 2 * q4;
            *(float2*)&Sg[r * 132 + o] = *(float2*)&ag[mt][nt][0];
            *(float2*)&Sg[(r + 8) * 132 + o] = *(float2*)&ag[mt][nt][2];
            *(float2*)&Sp[r * 132 + o] = *(float2*)&ap[mt][nt][0];
            *(float2*)&Sp[(r + 8) * 132 + o] = *(float2*)&ap[mt][nt][2];
        }
    }
    __syncthreads();
    const int mb = t * 256 + hp * 16;
#pragma unroll
    for (int u = 0; u < 2; u++) {
        int idx = u * 256 + tid;
        int p = idx >> 5, o4 = (idx & 31) * 4;
        float4 bgv = *(const float4*)&gb[o4];
        float4 bpv = *(const float4*)&pb[o4];
        float4 r0, r1, r2, r3, vo, ko;
        // g -> d_val
        r0 = *(float4*)&Sg[(2 * p) * 132 + o4];
        r1 = *(float4*)&Sg[(2 * p + 1) * 132 + o4];
        r2 = *(float4*)&Sg[(32 + 2 * p) * 132 + o4];
        r3 = *(float4*)&Sg[(33 + 2 * p) * 132 + o4];
        vo.x = fmaxf(fmaxf(r0.x, r1.x), fmaxf(r2.x, r3.x)) + bgv.x;
        vo.y = fmaxf(fmaxf(r0.y, r1.y), fmaxf(r2.y, r3.y)) + bgv.y;
        vo.z = fmaxf(fmaxf(r0.z, r1.z), fmaxf(r2.z, r3.z)) + bgv.z;
        vo.w = fmaxf(fmaxf(r0.w, r1.w), fmaxf(r2.w, r3.w)) + bgv.w;
        *(float4*)&d_val[((size_t)b * NKV_ + mb + p) * CI_ + o4] = vo;
        // phi -> d_key
        r0 = *(float4*)&Sp[(2 * p) * 132 + o4];
        r1 = *(float4*)&Sp[(2 * p + 1) * 132 + o4];
        r2 = *(float4*)&Sp[(32 + 2 * p) * 132 + o4];
        r3 = *(float4*)&Sp[(33 + 2 * p) * 132 + o4];
        ko.x = fmaxf(fmaxf(r0.x, r1.x), fmaxf(r2.x, r3.x)) + bpv.x;
        ko.y = fmaxf(fmaxf(r0.y, r1.y), fmaxf(r2.y, r3.y)) + bpv.y;
        ko.z = fmaxf(fmaxf(r0.z, r1.z), fmaxf(r2.z, r3.z)) + bpv.z;
        ko.w = fmaxf(fmaxf(r0.w, r1.w), fmaxf(r2.w, r3.w)) + bpv.w;
        *(float4*)&d_key[((size_t)b * NKV_ + mb + p) * CI_ + o4] = ko;
    }
}

// ---------------------------------------------------------------------------
// Kernel C: flash attention with tf32 mma.sync. grid (NQ/128, B), 256 thr.
// BQ=128, BK=64, d=128. 8 warps; warp w owns q rows [16w, 16w+16).
// ---------------------------------------------------------------------------
__global__ void __launch_bounds__(256, 1) attn_kernel() {
    extern __shared__ float sm[];
    float* Qs  = sm;                     // [128][132] tf32
    float* Ks  = Qs + 128 * 132;         // [64][132]  tf32, (kv, ci)
    float* VTs = Ks + 64 * 132;          // [128][68]  tf32, (ci, kv)
    float* Ps  = VTs + 128 * 68;         // [128][68]  tf32, (q, kv)
    const int b = blockIdx.y;
    const int qbase = blockIdx.x * 128;
    const int tid = threadIdx.x;
    const int warp = tid >> 5;
    const int lane = tid & 31;
    const int g = lane >> 2;
    const int q4 = lane & 3;
    const int r0 = warp * 16 + g;

#pragma unroll
    for (int u = 0; u < 16; u++) {
        int idx = u * 256 + tid;
        int r = idx >> 5, c4 = idx & 31;
        float4 v = *(const float4*)&d_theta[((size_t)b * NQ_ + qbase + r) * CI_ + c4 * 4];
        v.x = f2tf(v.x); v.y = f2tf(v.y); v.z = f2tf(v.z); v.w = f2tf(v.w);
        *(float4*)&Qs[r * 132 + c4 * 4] = v;
    }

    float m[2] = {-3.0e38f, -3.0e38f}, l[2] = {0.f, 0.f};
    float oacc[16][4];
#pragma unroll
    for (int i = 0; i < 16; i++)
#pragma unroll
        for (int j = 0; j < 4; j++) oacc[i][j] = 0.f;

    for (int mt = 0; mt < NKV_ / 64; mt++) {
        const int mbase = mt * 64;
        __syncthreads();
#pragma unroll
        for (int u = 0; u < 8; u++) {
            int idx = u * 256 + tid;
            int mm = idx >> 5, c4 = idx & 31;
            float4 kv = *(const float4*)&d_key[((size_t)b * NKV_ + mbase + mm) * CI_ + c4 * 4];
            kv.x = f2tf(kv.x); kv.y = f2tf(kv.y); kv.z = f2tf(kv.z); kv.w = f2tf(kv.w);
            *(float4*)&Ks[mm * 132 + c4 * 4] = kv;
            float4 vv = *(const float4*)&d_val[((size_t)b * NKV_ + mbase + mm) * CI_ + c4 * 4];
            VTs[(c4 * 4 + 0) * 68 + mm] = f2tf(vv.x);
            VTs[(c4 * 4 + 1) * 68 + mm] = f2tf(vv.y);
            VTs[(c4 * 4 + 2) * 68 + mm] = f2tf(vv.z);
            VTs[(c4 * 4 + 3) * 68 + mm] = f2tf(vv.w);
        }
        __syncthreads();

        float sacc[8][4];
#pragma unroll
        for (int i = 0; i < 8; i++)
#pragma unroll
            for (int j = 0; j < 4; j++) sacc[i][j] = 0.f;

#pragma unroll
        for (int ks = 0; ks < 16; ks++) {
            uint32_t a[4];
            int c0 = ks * 8 + q4;
            a[0] = __float_as_uint(Qs[r0 * 132 + c0]);
            a[1] = __float_as_uint(Qs[(r0 + 8) * 132 + c0]);
            a[2] = __float_as_uint(Qs[r0 * 132 + c0 + 4]);
            a[3] = __float_as_uint(Qs[(r0 + 8) * 132 + c0 + 4]);
#pragma unroll
            for (int nt = 0; nt < 8; nt++) {
                uint32_t bb[2];
                int n = nt * 8 + g;
                bb[0] = __float_as_uint(Ks[n * 132 + c0]);
                bb[1] = __float_as_uint(Ks[n * 132 + c0 + 4]);
                mma_tf32(sacc[nt], a, bb);
            }
        }

#pragma unroll
        for (int h = 0; h < 2; h++) {
            float tmax = -3.0e38f;
#pragma unroll
            for (int nt = 0; nt < 8; nt++)
                tmax = fmaxf(tmax, fmaxf(sacc[nt][2 * h], sacc[nt][2 * h + 1]));
            tmax = fmaxf(tmax, __shfl_xor_sync(0xffffffffu, tmax, 1));
            tmax = fmaxf(tmax, __shfl_xor_sync(0xffffffffu, tmax, 2));
            float nm = fmaxf(m[h], tmax);
            float fac = __expf(m[h] - nm);
            float s = 0.f;
#pragma unroll
            for (int nt = 0; nt < 8; nt++) {
                float e0 = __expf(sacc[nt][2 * h]     - nm);
                float e1 = __expf(sacc[nt][2 * h + 1] - nm);
                sacc[nt][2 * h] = e0; sacc[nt][2 * h + 1] = e1;
                s += e0 + e1;
            }
            s += __shfl_xor_sync(0xffffffffu, s, 1);
            s += __shfl_xor_sync(0xffffffffu, s, 2);
            l[h] = l[h] * fac + s;
            m[h] = nm;
#pragma unroll
            for (int ot = 0; ot < 16; ot++) {
                oacc[ot][2 * h]     *= fac;
                oacc[ot][2 * h + 1] *= fac;
            }
        }

#pragma unroll
        for (int nt = 0; nt < 8; nt++) {
            int cb = nt * 8 + 2 * q4;
            Ps[r0 * 68 + cb]           = f2tf(sacc[nt][0]);
            Ps[r0 * 68 + cb + 1]       = f2tf(sacc[nt][1]);
            Ps[(r0 + 8) * 68 + cb]     = f2tf(sacc[nt][2]);
            Ps[(r0 + 8) * 68 + cb + 1] = f2tf(sacc[nt][3]);
        }
        __syncwarp();

#pragma unroll
        for (int ks = 0; ks < 8; ks++) {
            uint32_t a[4];
            int kk = ks * 8 + q4;
            a[0] = __float_as_uint(Ps[r0 * 68 + kk]);
            a[1] = __float_as_uint(Ps[(r0 + 8) * 68 + kk]);
            a[2] = __float_as_uint(Ps[r0 * 68 + kk + 4]);
            a[3] = __float_as_uint(Ps[(r0 + 8) * 68 + kk + 4]);
#pragma unroll
            for (int nt = 0; nt < 16; nt++) {
                uint32_t bb[2];
                int n = nt * 8 + g;
                bb[0] = __float_as_uint(VTs[n * 68 + kk]);
                bb[1] = __float_as_uint(VTs[n * 68 + kk + 4]);
                mma_tf32(oacc[nt], a, bb);
            }
        }
    }

    // epilogue: normalize, write directly to d_yy (b, n, ci)
    float inv0 = 1.f / l[0], inv1 = 1.f / l[1];
    size_t row0 = (size_t)b * NQ_ + qbase + r0;
#pragma unroll
    for (int nt = 0; nt < 16; nt++) {
        int ci = nt * 8 + 2 * q4;
        float2 v0 = {oacc[nt][0] * inv0, oacc[nt][1] * inv0};
        float2 v1 = {oacc[nt][2] * inv1, oacc[nt][3] * inv1};
        *(float2*)&d_yy[row0 * CI_ + ci] = v0;
        *(float2*)&d_yy[(row0 + 8) * CI_ + ci] = v1;
    }
}

// ---------------------------------------------------------------------------
// Kernel D: out = scale*(w_w @ yy + w_b) + shift + x
// GEMM: M=co(128), N=n(128), K=ci(128, chunks of 64). tf32 MMA.
// grid (NQ/128, C/128, B), 256 threads (8 warps, 2 M x 4 N).
// ---------------------------------------------------------------------------
__global__ void __launch_bounds__(256) wconv_kernel(
        const float* __restrict__ x,
        const float* __restrict__ ww, const float* __restrict__ wb,
        const float* __restrict__ bng, const float* __restrict__ bnb,
        const float* __restrict__ bnm, const float* __restrict__ bnv,
        float* __restrict__ out) {
    extern __shared__ float sm[];
    float* Ws = sm;              // [128 co][68]
    float* Ys = sm + 128 * 68;   // [128 n][68]
    const int b = blockIdx.z;
    const int cobase = blockIdx.y * 128;
    const int nbase = blockIdx.x * 128;
    const int tid = threadIdx.x;
    const int warp = tid >> 5, lane = tid & 31;
    const int g = lane >> 2, q4 = lane & 3;
    const int m0 = (warp >> 2) * 64;
    const int n0 = (warp & 3) * 32;

    float acc[4][4][4];
#pragma unroll
    for (int i = 0; i < 4; i++)
#pragma unroll
        for (int j = 0; j < 4; j++)
#pragma unroll
            for (int k = 0; k < 4; k++) acc[i][j][k] = 0.f;

    for (int c0 = 0; c0 < CI_; c0 += 64) {
        __syncthreads();
#pragma unroll
        for (int u = 0; u < 8; u++) {
            int idx = u * 256 + tid;
            int rr = idx >> 4, c4 = idx & 15;
            float4 w = *(const float4*)&ww[(cobase + rr) * CI_ + c0 + c4 * 4];
            w.x = f2tf(w.x); w.y = f2tf(w.y); w.z = f2tf(w.z); w.w = f2tf(w.w);
            *(float4*)&Ws[rr * 68 + c4 * 4] = w;
            float4 y = *(const float4*)&d_yy[((size_t)b * NQ_ + nbase + rr) * CI_ + c0 + c4 * 4];
            y.x = f2tf(y.x); y.y = f2tf(y.y); y.z = f2tf(y.z); y.w = f2tf(y.w);
            *(float4*)&Ys[rr * 68 + c4 * 4] = y;
        }
        __syncthreads();
#pragma unroll
        for (int ks = 0; ks < 8; ks++) {
            int k = ks * 8;
            uint32_t a[4][4];
#pragma unroll
            for (int mt = 0; mt < 4; mt++) {
                int r = m0 + mt * 16 + g;
                a[mt][0] = __float_as_uint(Ws[r * 68 + k + q4]);
                a[mt][1] = __float_as_uint(Ws[(r + 8) * 68 + k + q4]);
                a[mt][2] = __float_as_uint(Ws[r * 68 + k + q4 + 4]);
                a[mt][3] = __float_as_uint(Ws[(r + 8) * 68 + k + q4 + 4]);
            }
#pragma unroll
            for (int nt = 0; nt < 4; nt++) {
                uint32_t bb[2];
                int n = n0 + nt * 8 + g;
                bb[0] = __float_as_uint(Ys[n * 68 + k + q4]);
                bb[1] = __float_as_uint(Ys[n * 68 + k + q4 + 4]);
#pragma unroll
                for (int mt = 0; mt < 4; mt++) mma_tf32(acc[mt][nt], a[mt], bb);
            }
        }
    }

    // epilogue: BN affine + bias + residual
    float sc[4][2], sh[4][2];
#pragma unroll
    for (int mt = 0; mt < 4; mt++)
#pragma unroll
        for (int h = 0; h < 2; h++) {
            int co = cobase + m0 + mt * 16 + g + h * 8;
            float s = bng[co] * rsqrtf(bnv[co] + 1e-5f);
            sc[mt][h] = s;
            sh[mt][h] = bnb[co] - bnm[co] * s + s * wb[co];
        }
#pragma unroll
    for (int mt = 0; mt < 4; mt++) {
#pragma unroll
        for (int nt = 0; nt < 4; nt++) {
            int n = nbase + n0 + nt * 8 + 2 * q4;
#pragma unroll
            for (int h = 0; h < 2; h++) {
                int co = cobase + m0 + mt * 16 + g + h * 8;
                size_t base = ((size_t)b * C_ + co) * NQ_ + n;
                float2 xv = *(const float2*)&x[base];
                float2 o;
                o.x = acc[mt][nt][2 * h]     * sc[mt][h] + sh[mt][h] + xv.x;
                o.y = acc[mt][nt][2 * h + 1] * sc[mt][h] + sh[mt][h] + xv.y;
                *(float2*)&out[base] = o;
            }
        }
    }
}

// ---------------------------------------------------------------------------
extern "C" void kernel_launch(void* const* d_in, const int* in_sizes, int n_in,
                              void* d_out, int out_size) {
    const float* x    = (const float*)d_in[0];
    const float* g_w  = (const float*)d_in[1];
    const float* g_b  = (const float*)d_in[2];
    const float* th_w = (const float*)d_in[3];
    const float* th_b = (const float*)d_in[4];
    const float* ph_w = (const float*)d_in[5];
    const float* ph_b = (const float*)d_in[6];
    const float* w_w  = (const float*)d_in[7];
    const float* w_b  = (const float*)d_in[8];
    const float* bn_g = (const float*)d_in[9];
    const float* bn_b = (const float*)d_in[10];
    const float* bn_m = (const float*)d_in[11];
    const float* bn_v = (const float*)d_in[12];
    float* out = (float*)d_out;

    const int smA = 2 * 128 * 68 * 4;                                 // 69632
    const int smB = (64 * 68 + 2 * 128 * 68) * 4;                     // 87040
    const int smC = (128 * 132 + 64 * 132 + 128 * 68 + 128 * 68) * 4; // 171008
    const int smD = 2 * 128 * 68 * 4;                                 // 69632

    cudaFuncSetAttribute(conv_theta_kernel, cudaFuncAttributeMaxDynamicSharedMemorySize, smA);
    cudaFuncSetAttribute(conv_gphi_kernel,  cudaFuncAttributeMaxDynamicSharedMemorySize, smB);
    cudaFuncSetAttribute(attn_kernel,       cudaFuncAttributeMaxDynamicSharedMemorySize, smC);
    cudaFuncSetAttribute(wconv_kernel,      cudaFuncAttributeMaxDynamicSharedMemorySize, smD);

    conv_theta_kernel<<<dim3(NQ_ / 128, B_), 256, smA>>>(x, th_w, th_b);
    conv_gphi_kernel<<<dim3(128, B_), 256, smB>>>(x, g_w, g_b, ph_w, ph_b);
    attn_kernel<<<dim3(NQ_ / 128, B_), 256, smC>>>();
    wconv_kernel<<<dim3(NQ_ / 128, C_ / 128, B_), 256, smD>>>(x, w_w, w_b,
                                                              bn_g, bn_b, bn_m, bn_v, out);
}

// round 5
// speedup vs baseline: 4.5601x; 1.3964x over previous
#include <cuda_runtime.h>
#include <math.h>
#include <stdint.h>

#define B_  4
#define C_  256
#define CI_ 128
#define NQ_ 8192
#define NKV_ 2048

// scratch (no cudaMalloc allowed)
__device__ float d_theta[(size_t)B_ * NQ_ * CI_];   // (b, n, ci)   tf32-rounded
__device__ float d_key  [(size_t)B_ * NKV_ * CI_];  // (b, m, ci)   tf32-rounded
__device__ float d_valT [(size_t)B_ * CI_ * NKV_];  // (b, ci, m)   tf32-rounded
__device__ float d_yy   [(size_t)B_ * NQ_ * CI_];   // (b, n, ci)   fp32

__device__ __forceinline__ float f2tf(float f) {
    uint32_t u;
    asm("cvt.rna.tf32.f32 %0, %1;" : "=r"(u) : "f"(f));
    return __uint_as_float(u);
}

__device__ __forceinline__ void mma_tf32(float* c, const uint32_t* a, const uint32_t* b) {
    asm volatile(
        "mma.sync.aligned.m16n8k8.row.col.f32.tf32.tf32.f32 "
        "{%0,%1,%2,%3}, {%4,%5,%6,%7}, {%8,%9}, {%0,%1,%2,%3};"
        : "+f"(c[0]), "+f"(c[1]), "+f"(c[2]), "+f"(c[3])
        : "r"(a[0]), "r"(a[1]), "r"(a[2]), "r"(a[3]), "r"(b[0]), "r"(b[1]));
}

__device__ __forceinline__ void ldsm_x4(uint32_t* r, uint32_t a) {
    asm volatile("ldmatrix.sync.aligned.m8n8.x4.shared.b16 {%0,%1,%2,%3}, [%4];"
                 : "=r"(r[0]), "=r"(r[1]), "=r"(r[2]), "=r"(r[3]) : "r"(a));
}

// ---------------------------------------------------------------------------
// Kernel A: theta = conv1x1(x, theta_w) + theta_b -> d_theta (b, n, ci) tf32
// ---------------------------------------------------------------------------
__global__ void __launch_bounds__(256) conv_theta_kernel(
        const float* __restrict__ x,
        const float* __restrict__ tw,
        const float* __restrict__ tb) {
    extern __shared__ float sm[];
    float* Xs = sm;              // [128 n][68]
    float* Ws = sm + 128 * 68;   // [128 o][68]
    const int b = blockIdx.y;
    const int nbase = blockIdx.x * 128;
    const int tid = threadIdx.x;
    const int warp = tid >> 5, lane = tid & 31;
    const int g = lane >> 2, q4 = lane & 3;
    const int m0 = (warp >> 2) * 64;
    const int n0 = (warp & 3) * 32;

    float acc[4][4][4];
#pragma unroll
    for (int i = 0; i < 4; i++)
#pragma unroll
        for (int j = 0; j < 4; j++)
#pragma unroll
            for (int k = 0; k < 4; k++) acc[i][j][k] = 0.f;

    for (int c0 = 0; c0 < C_; c0 += 64) {
        __syncthreads();
#pragma unroll
        for (int u = 0; u < 8; u++) {
            int idx = u * 256 + tid;
            int cc = idx >> 5, j4 = idx & 31;
            float4 v = *(const float4*)&x[((size_t)b * C_ + c0 + cc) * NQ_ + nbase + j4 * 4];
            Xs[(j4 * 4 + 0) * 68 + cc] = f2tf(v.x);
            Xs[(j4 * 4 + 1) * 68 + cc] = f2tf(v.y);
            Xs[(j4 * 4 + 2) * 68 + cc] = f2tf(v.z);
            Xs[(j4 * 4 + 3) * 68 + cc] = f2tf(v.w);
        }
#pragma unroll
        for (int u = 0; u < 8; u++) {
            int idx = u * 256 + tid;
            int oo = idx >> 4, c4 = idx & 15;
            float4 w = *(const float4*)&tw[oo * C_ + c0 + c4 * 4];
            w.x = f2tf(w.x); w.y = f2tf(w.y); w.z = f2tf(w.z); w.w = f2tf(w.w);
            *(float4*)&Ws[oo * 68 + c4 * 4] = w;
        }
        __syncthreads();
#pragma unroll
        for (int ks = 0; ks < 8; ks++) {
            int k = ks * 8;
            uint32_t a[4][4];
#pragma unroll
            for (int mt = 0; mt < 4; mt++) {
                int r = m0 + mt * 16 + g;
                a[mt][0] = __float_as_uint(Xs[r * 68 + k + q4]);
                a[mt][1] = __float_as_uint(Xs[(r + 8) * 68 + k + q4]);
                a[mt][2] = __float_as_uint(Xs[r * 68 + k + q4 + 4]);
                a[mt][3] = __float_as_uint(Xs[(r + 8) * 68 + k + q4 + 4]);
            }
#pragma unroll
            for (int nt = 0; nt < 4; nt++) {
                uint32_t bb[2];
                int n = n0 + nt * 8 + g;
                bb[0] = __float_as_uint(Ws[n * 68 + k + q4]);
                bb[1] = __float_as_uint(Ws[n * 68 + k + q4 + 4]);
#pragma unroll
                for (int mt = 0; mt < 4; mt++) mma_tf32(acc[mt][nt], a[mt], bb);
            }
        }
    }
#pragma unroll
    for (int nt = 0; nt < 4; nt++) {
        int o = n0 + nt * 8 + 2 * q4;
        float b0 = tb[o], b1 = tb[o + 1];
#pragma unroll
        for (int mt = 0; mt < 4; mt++) {
            size_t r = (size_t)b * NQ_ + nbase + m0 + mt * 16 + g;
            float2 v0 = {f2tf(acc[mt][nt][0] + b0), f2tf(acc[mt][nt][1] + b1)};
            float2 v1 = {f2tf(acc[mt][nt][2] + b0), f2tf(acc[mt][nt][3] + b1)};
            *(float2*)&d_theta[r * CI_ + o] = v0;
            *(float2*)&d_theta[(r + 8) * CI_ + o] = v1;
        }
    }
}

// ---------------------------------------------------------------------------
// Kernel B: g/phi conv1x1 + maxpool(1,2,2) -> d_valT (b,ci,m) / d_key (b,m,ci)
// ---------------------------------------------------------------------------
__global__ void __launch_bounds__(256) conv_gphi_kernel(
        const float* __restrict__ x,
        const float* __restrict__ gw, const float* __restrict__ gb,
        const float* __restrict__ pw, const float* __restrict__ pb) {
    extern __shared__ float sm[];
    float* Xs = sm;               // [64 n][68]
    float* Wg = sm + 64 * 68;     // [128 o][68]
    float* Wp = Wg + 128 * 68;    // [128 o][68]
    const int b = blockIdx.y;
    const int t = blockIdx.x >> 4, hp = blockIdx.x & 15;
    const int nbase = t * 1024 + hp * 64;
    const int tid = threadIdx.x;
    const int warp = tid >> 5, lane = tid & 31;
    const int g = lane >> 2, q4 = lane & 3;
    const int m0 = (warp >> 2) * 32;
    const int n0 = (warp & 3) * 32;

    float ag[2][4][4], ap[2][4][4];
#pragma unroll
    for (int i = 0; i < 2; i++)
#pragma unroll
        for (int j = 0; j < 4; j++)
#pragma unroll
            for (int k = 0; k < 4; k++) { ag[i][j][k] = 0.f; ap[i][j][k] = 0.f; }

    for (int c0 = 0; c0 < C_; c0 += 64) {
        __syncthreads();
#pragma unroll
        for (int u = 0; u < 4; u++) {
            int idx = u * 256 + tid;
            int cc = idx >> 4, j4 = idx & 15;
            float4 v = *(const float4*)&x[((size_t)b * C_ + c0 + cc) * NQ_ + nbase + j4 * 4];
            Xs[(j4 * 4 + 0) * 68 + cc] = f2tf(v.x);
            Xs[(j4 * 4 + 1) * 68 + cc] = f2tf(v.y);
            Xs[(j4 * 4 + 2) * 68 + cc] = f2tf(v.z);
            Xs[(j4 * 4 + 3) * 68 + cc] = f2tf(v.w);
        }
#pragma unroll
        for (int u = 0; u < 8; u++) {
            int idx = u * 256 + tid;
            int oo = idx >> 4, c4 = idx & 15;
            float4 w = *(const float4*)&gw[oo * C_ + c0 + c4 * 4];
            w.x = f2tf(w.x); w.y = f2tf(w.y); w.z = f2tf(w.z); w.w = f2tf(w.w);
            *(float4*)&Wg[oo * 68 + c4 * 4] = w;
            float4 p = *(const float4*)&pw[oo * C_ + c0 + c4 * 4];
            p.x = f2tf(p.x); p.y = f2tf(p.y); p.z = f2tf(p.z); p.w = f2tf(p.w);
            *(float4*)&Wp[oo * 68 + c4 * 4] = p;
        }
        __syncthreads();
#pragma unroll
        for (int ks = 0; ks < 8; ks++) {
            int k = ks * 8;
            uint32_t a[2][4];
#pragma unroll
            for (int mt = 0; mt < 2; mt++) {
                int r = m0 + mt * 16 + g;
                a[mt][0] = __float_as_uint(Xs[r * 68 + k + q4]);
                a[mt][1] = __float_as_uint(Xs[(r + 8) * 68 + k + q4]);
                a[mt][2] = __float_as_uint(Xs[r * 68 + k + q4 + 4]);
                a[mt][3] = __float_as_uint(Xs[(r + 8) * 68 + k + q4 + 4]);
            }
#pragma unroll
            for (int nt = 0; nt < 4; nt++) {
                int n = n0 + nt * 8 + g;
                uint32_t bg_[2], bp_[2];
                bg_[0] = __float_as_uint(Wg[n * 68 + k + q4]);
                bg_[1] = __float_as_uint(Wg[n * 68 + k + q4 + 4]);
                bp_[0] = __float_as_uint(Wp[n * 68 + k + q4]);
                bp_[1] = __float_as_uint(Wp[n * 68 + k + q4 + 4]);
#pragma unroll
                for (int mt = 0; mt < 2; mt++) {
                    mma_tf32(ag[mt][nt], a[mt], bg_);
                    mma_tf32(ap[mt][nt], a[mt], bp_);
                }
            }
        }
    }
    // stage raw S tiles
    __syncthreads();
    float* Sg = sm;                 // [64][132]
    float* Sp = sm + 64 * 132;      // [64][132]
    float* Pv = sm + 2 * 64 * 132;  // [128][20] pooled g transposed (ci, m)
#pragma unroll
    for (int mt = 0; mt < 2; mt++) {
#pragma unroll
        for (int nt = 0; nt < 4; nt++) {
            int r = m0 + mt * 16 + g;
            int o = n0 + nt * 8 + 2 * q4;
            *(float2*)&Sg[r * 132 + o] = *(float2*)&ag[mt][nt][0];
            *(float2*)&Sg[(r + 8) * 132 + o] = *(float2*)&ag[mt][nt][2];
            *(float2*)&Sp[r * 132 + o] = *(float2*)&ap[mt][nt][0];
            *(float2*)&Sp[(r + 8) * 132 + o] = *(float2*)&ap[mt][nt][2];
        }
    }
    __syncthreads();
    const int mb = t * 256 + hp * 16;
#pragma unroll
    for (int u = 0; u < 2; u++) {
        int idx = u * 256 + tid;
        int p = idx >> 5, o4 = (idx & 31) * 4;
        float4 bgv = *(const float4*)&gb[o4];
        float4 bpv = *(const float4*)&pb[o4];
        float4 r0, r1, r2, r3;
        // phi -> d_key (m, ci), tf32
        r0 = *(float4*)&Sp[(2 * p) * 132 + o4];
        r1 = *(float4*)&Sp[(2 * p + 1) * 132 + o4];
        r2 = *(float4*)&Sp[(32 + 2 * p) * 132 + o4];
        r3 = *(float4*)&Sp[(33 + 2 * p) * 132 + o4];
        float4 ko;
        ko.x = f2tf(fmaxf(fmaxf(r0.x, r1.x), fmaxf(r2.x, r3.x)) + bpv.x);
        ko.y = f2tf(fmaxf(fmaxf(r0.y, r1.y), fmaxf(r2.y, r3.y)) + bpv.y);
        ko.z = f2tf(fmaxf(fmaxf(r0.z, r1.z), fmaxf(r2.z, r3.z)) + bpv.z);
        ko.w = f2tf(fmaxf(fmaxf(r0.w, r1.w), fmaxf(r2.w, r3.w)) + bpv.w);
        *(float4*)&d_key[((size_t)b * NKV_ + mb + p) * CI_ + o4] = ko;
        // g -> Pv transposed staging (ci, m), tf32
        r0 = *(float4*)&Sg[(2 * p) * 132 + o4];
        r1 = *(float4*)&Sg[(2 * p + 1) * 132 + o4];
        r2 = *(float4*)&Sg[(32 + 2 * p) * 132 + o4];
        r3 = *(float4*)&Sg[(33 + 2 * p) * 132 + o4];
        Pv[(o4 + 0) * 20 + p] = f2tf(fmaxf(fmaxf(r0.x, r1.x), fmaxf(r2.x, r3.x)) + bgv.x);
        Pv[(o4 + 1) * 20 + p] = f2tf(fmaxf(fmaxf(r0.y, r1.y), fmaxf(r2.y, r3.y)) + bgv.y);
        Pv[(o4 + 2) * 20 + p] = f2tf(fmaxf(fmaxf(r0.z, r1.z), fmaxf(r2.z, r3.z)) + bgv.z);
        Pv[(o4 + 3) * 20 + p] = f2tf(fmaxf(fmaxf(r0.w, r1.w), fmaxf(r2.w, r3.w)) + bgv.w);
    }
    __syncthreads();
#pragma unroll
    for (int u = 0; u < 2; u++) {
        int idx = u * 256 + tid;           // 0..511
        int ci = idx >> 2, j = (idx & 3) * 4;
        float4 v = {Pv[ci * 20 + j], Pv[ci * 20 + j + 1],
                    Pv[ci * 20 + j + 2], Pv[ci * 20 + j + 3]};
        *(float4*)&d_valT[((size_t)b * CI_ + ci) * NKV_ + mb + j] = v;
    }
}

// ---------------------------------------------------------------------------
// Kernel C: flash attention. BQ=128, BK=64, d=128. 8 warps.
// Q fragments in registers; ldmatrix for K/P/V; cp.async double buffer.
// smem floats: K0[64][132]@0  K1@8448  V0[128][68]@16896  V1@25600  Ps[128][68]@34304
// ---------------------------------------------------------------------------
__device__ __forceinline__ void cp_tile(uint32_t kdst, uint32_t vdst,
        const float* __restrict__ keyb, const float* __restrict__ valb,
        int mbase, int tid) {
#pragma unroll
    for (int u = 0; u < 8; u++) {
        int idx = u * 256 + tid;
        int r = idx >> 5, c = idx & 31;
        uint32_t d = kdst + (uint32_t)(r * 132 + c * 4) * 4u;
        const float* s = keyb + (size_t)(mbase + r) * CI_ + c * 4;
        asm volatile("cp.async.cg.shared.global [%0], [%1], 16;" :: "r"(d), "l"(s));
    }
#pragma unroll
    for (int u = 0; u < 8; u++) {
        int idx = u * 256 + tid;
        int r = idx >> 4, c = idx & 15;
        uint32_t d = vdst + (uint32_t)(r * 68 + c * 4) * 4u;
        const float* s = valb + (size_t)r * NKV_ + mbase + c * 4;
        asm volatile("cp.async.cg.shared.global [%0], [%1], 16;" :: "r"(d), "l"(s));
    }
}

__global__ void __launch_bounds__(256, 1) attn_kernel() {
    extern __shared__ float sm[];
    const int b = blockIdx.y;
    const int qbase = blockIdx.x * 128;
    const int tid = threadIdx.x;
    const int warp = tid >> 5;
    const int lane = tid & 31;
    const int g = lane >> 2, q4 = lane & 3;
    const int r0 = warp * 16 + g;
    const uint32_t smb = (uint32_t)__cvta_generic_to_shared(sm);

    float* Ps = sm + 34304;   // [128][68]

    // ---- prologue: stage Q (reusing K region), ldmatrix into registers ----
    {
        const float* src = &d_theta[((size_t)b * NQ_ + qbase) * CI_];
#pragma unroll
        for (int u = 0; u < 16; u++) {
            int idx = u * 256 + tid;
            int r = idx >> 5, c4 = idx & 31;
            *(float4*)&sm[r * 132 + c4 * 4] = *(const float4*)&src[r * CI_ + c4 * 4];
        }
    }
    __syncthreads();
    uint32_t qfrag[16][4];
    {
        uint32_t qa = smb + (uint32_t)((warp * 16 + (lane & 7) + ((lane >> 3) & 1) * 8) * 132
                                       + ((lane >> 4) ? 4 : 0)) * 4u;
#pragma unroll
        for (int ks = 0; ks < 16; ks++) ldsm_x4(qfrag[ks], qa + ks * 32);
    }
    __syncthreads();

    // lane-base offsets (in floats) for B-fragment ldmatrix
    const uint32_t kK = ((lane & 7) + ((lane >> 4) & 1) * 8) * 132 + ((lane >> 3) & 1) * 4;
    const uint32_t kV = ((lane & 7) + ((lane >> 4) & 1) * 8) * 68 + ((lane >> 3) & 1) * 4;
    const uint32_t pa = (uint32_t)((warp * 16 + (lane & 7) + ((lane >> 3) & 1) * 8) * 68
                                   + ((lane >> 4) ? 4 : 0));
    const uint32_t KbA[2] = {smb, smb + 8448u * 4};
    const uint32_t VbA[2] = {smb + 16896u * 4, smb + 25600u * 4};
    const uint32_t PsA = smb + 34304u * 4;

    const float* keyb = &d_key[(size_t)b * NKV_ * CI_];
    const float* valb = &d_valT[(size_t)b * CI_ * NKV_];

    cp_tile(KbA[0], VbA[0], keyb, valb, 0, tid);
    asm volatile("cp.async.commit_group;");

    float m[2] = {-3.0e38f, -3.0e38f}, l[2] = {0.f, 0.f};
    float oacc[16][4];
#pragma unroll
    for (int i = 0; i < 16; i++)
#pragma unroll
        for (int j = 0; j < 4; j++) oacc[i][j] = 0.f;

    for (int mt = 0; mt < NKV_ / 64; mt++) {
        asm volatile("cp.async.wait_group 0;");
        __syncthreads();
        if (mt + 1 < NKV_ / 64) {
            cp_tile(KbA[(mt + 1) & 1], VbA[(mt + 1) & 1], keyb, valb, (mt + 1) * 64, tid);
            asm volatile("cp.async.commit_group;");
        }
        const uint32_t Ka = KbA[mt & 1] + kK * 4;
        const uint32_t Va = VbA[mt & 1] + kV * 4;

        float sacc[8][4];
#pragma unroll
        for (int i = 0; i < 8; i++)
#pragma unroll
            for (int j = 0; j < 4; j++) sacc[i][j] = 0.f;

#pragma unroll
        for (int ks = 0; ks < 16; ks++) {
#pragma unroll
            for (int ntp = 0; ntp < 4; ntp++) {
                uint32_t bb[4];
                ldsm_x4(bb, Ka + (uint32_t)(ntp * 16 * 132 + ks * 8) * 4u);
                mma_tf32(sacc[2 * ntp], qfrag[ks], bb);
                mma_tf32(sacc[2 * ntp + 1], qfrag[ks], bb + 2);
            }
        }

        // online softmax
#pragma unroll
        for (int h = 0; h < 2; h++) {
            float tmax = -3.0e38f;
#pragma unroll
            for (int nt = 0; nt < 8; nt++)
                tmax = fmaxf(tmax, fmaxf(sacc[nt][2 * h], sacc[nt][2 * h + 1]));
            tmax = fmaxf(tmax, __shfl_xor_sync(0xffffffffu, tmax, 1));
            tmax = fmaxf(tmax, __shfl_xor_sync(0xffffffffu, tmax, 2));
            float nm = fmaxf(m[h], tmax);
            float fac = __expf(m[h] - nm);
            float s = 0.f;
#pragma unroll
            for (int nt = 0; nt < 8; nt++) {
                float e0 = __expf(sacc[nt][2 * h] - nm);
                float e1 = __expf(sacc[nt][2 * h + 1] - nm);
                sacc[nt][2 * h] = e0; sacc[nt][2 * h + 1] = e1;
                s += e0 + e1;
            }
            s += __shfl_xor_sync(0xffffffffu, s, 1);
            s += __shfl_xor_sync(0xffffffffu, s, 2);
            l[h] = l[h] * fac + s;
            m[h] = nm;
#pragma unroll
            for (int ot = 0; ot < 16; ot++) {
                oacc[ot][2 * h]     *= fac;
                oacc[ot][2 * h + 1] *= fac;
            }
        }

        // store P (own-warp rows only)
#pragma unroll
        for (int nt = 0; nt < 8; nt++) {
            int cb = nt * 8 + 2 * q4;
            Ps[r0 * 68 + cb]           = f2tf(sacc[nt][0]);
            Ps[r0 * 68 + cb + 1]       = f2tf(sacc[nt][1]);
            Ps[(r0 + 8) * 68 + cb]     = f2tf(sacc[nt][2]);
            Ps[(r0 + 8) * 68 + cb + 1] = f2tf(sacc[nt][3]);
        }
        __syncwarp();

        // O += P V
#pragma unroll
        for (int ks = 0; ks < 8; ks++) {
            uint32_t a[4];
            ldsm_x4(a, PsA + (pa + ks * 8) * 4u);
#pragma unroll
            for (int ntp = 0; ntp < 8; ntp++) {
                uint32_t bb[4];
                ldsm_x4(bb, Va + (uint32_t)(ntp * 16 * 68 + ks * 8) * 4u);
                mma_tf32(oacc[2 * ntp], a, bb);
                mma_tf32(oacc[2 * ntp + 1], a, bb + 2);
            }
        }
    }

    // epilogue: normalize, write d_yy (b, n, ci)
    float inv0 = 1.f / l[0], inv1 = 1.f / l[1];
    size_t row0 = (size_t)b * NQ_ + qbase + r0;
#pragma unroll
    for (int nt = 0; nt < 16; nt++) {
        int ci = nt * 8 + 2 * q4;
        float2 v0 = {oacc[nt][0] * inv0, oacc[nt][1] * inv0};
        float2 v1 = {oacc[nt][2] * inv1, oacc[nt][3] * inv1};
        *(float2*)&d_yy[row0 * CI_ + ci] = v0;
        *(float2*)&d_yy[(row0 + 8) * CI_ + ci] = v1;
    }
}

// ---------------------------------------------------------------------------
// Kernel D: out = scale*(w_w @ yy + w_b) + shift + x
// ---------------------------------------------------------------------------
__global__ void __launch_bounds__(256) wconv_kernel(
        const float* __restrict__ x,
        const float* __restrict__ ww, const float* __restrict__ wb,
        const float* __restrict__ bng, const float* __restrict__ bnb,
        const float* __restrict__ bnm, const float* __restrict__ bnv,
        float* __restrict__ out) {
    extern __shared__ float sm[];
    float* Ws = sm;              // [128 co][68]
    float* Ys = sm + 128 * 68;   // [128 n][68]
    const int b = blockIdx.z;
    const int cobase = blockIdx.y * 128;
    const int nbase = blockIdx.x * 128;
    const int tid = threadIdx.x;
    const int warp = tid >> 5, lane = tid & 31;
    const int g = lane >> 2, q4 = lane & 3;
    const int m0 = (warp >> 2) * 64;
    const int n0 = (warp & 3) * 32;

    float acc[4][4][4];
#pragma unroll
    for (int i = 0; i < 4; i++)
#pragma unroll
        for (int j = 0; j < 4; j++)
#pragma unroll
            for (int k = 0; k < 4; k++) acc[i][j][k] = 0.f;

    for (int c0 = 0; c0 < CI_; c0 += 64) {
        __syncthreads();
#pragma unroll
        for (int u = 0; u < 8; u++) {
            int idx = u * 256 + tid;
            int rr = idx >> 4, c4 = idx & 15;
            float4 w = *(const float4*)&ww[(cobase + rr) * CI_ + c0 + c4 * 4];
            w.x = f2tf(w.x); w.y = f2tf(w.y); w.z = f2tf(w.z); w.w = f2tf(w.w);
            *(float4*)&Ws[rr * 68 + c4 * 4] = w;
            float4 y = *(const float4*)&d_yy[((size_t)b * NQ_ + nbase + rr) * CI_ + c0 + c4 * 4];
            y.x = f2tf(y.x); y.y = f2tf(y.y); y.z = f2tf(y.z); y.w = f2tf(y.w);
            *(float4*)&Ys[rr * 68 + c4 * 4] = y;
        }
        __syncthreads();
#pragma unroll
        for (int ks = 0; ks < 8; ks++) {
            int k = ks * 8;
            uint32_t a[4][4];
#pragma unroll
            for (int mt = 0; mt < 4; mt++) {
                int r = m0 + mt * 16 + g;
                a[mt][0] = __float_as_uint(Ws[r * 68 + k + q4]);
                a[mt][1] = __float_as_uint(Ws[(r + 8) * 68 + k + q4]);
                a[mt][2] = __float_as_uint(Ws[r * 68 + k + q4 + 4]);
                a[mt][3] = __float_as_uint(Ws[(r + 8) * 68 + k + q4 + 4]);
            }
#pragma unroll
            for (int nt = 0; nt < 4; nt++) {
                uint32_t bb[2];
                int n = n0 + nt * 8 + g;
                bb[0] = __float_as_uint(Ys[n * 68 + k + q4]);
                bb[1] = __float_as_uint(Ys[n * 68 + k + q4 + 4]);
#pragma unroll
                for (int mt = 0; mt < 4; mt++) mma_tf32(acc[mt][nt], a[mt], bb);
            }
        }
    }

    float sc[4][2], sh[4][2];
#pragma unroll
    for (int mt = 0; mt < 4; mt++)
#pragma unroll
        for (int h = 0; h < 2; h++) {
            int co = cobase + m0 + mt * 16 + g + h * 8;
            float s = bng[co] * rsqrtf(bnv[co] + 1e-5f);
            sc[mt][h] = s;
            sh[mt][h] = bnb[co] - bnm[co] * s + s * wb[co];
        }
#pragma unroll
    for (int mt = 0; mt < 4; mt++) {
#pragma unroll
        for (int nt = 0; nt < 4; nt++) {
            int n = nbase + n0 + nt * 8 + 2 * q4;
#pragma unroll
            for (int h = 0; h < 2; h++) {
                int co = cobase + m0 + mt * 16 + g + h * 8;
                size_t base = ((size_t)b * C_ + co) * NQ_ + n;
                float2 xv = *(const float2*)&x[base];
                float2 o;
                o.x = acc[mt][nt][2 * h]     * sc[mt][h] + sh[mt][h] + xv.x;
                o.y = acc[mt][nt][2 * h + 1] * sc[mt][h] + sh[mt][h] + xv.y;
                *(float2*)&out[base] = o;
            }
        }
    }
}

// ---------------------------------------------------------------------------
extern "C" void kernel_launch(void* const* d_in, const int* in_sizes, int n_in,
                              void* d_out, int out_size) {
    const float* x    = (const float*)d_in[0];
    const float* g_w  = (const float*)d_in[1];
    const float* g_b  = (const float*)d_in[2];
    const float* th_w = (const float*)d_in[3];
    const float* th_b = (const float*)d_in[4];
    const float* ph_w = (const float*)d_in[5];
    const float* ph_b = (const float*)d_in[6];
    const float* w_w  = (const float*)d_in[7];
    const float* w_b  = (const float*)d_in[8];
    const float* bn_g = (const float*)d_in[9];
    const float* bn_b = (const float*)d_in[10];
    const float* bn_m = (const float*)d_in[11];
    const float* bn_v = (const float*)d_in[12];
    float* out = (float*)d_out;

    const int smA = 2 * 128 * 68 * 4;                 // 69632
    const int smB = (64 * 68 + 2 * 128 * 68) * 4;     // 87040
    const int smC = (2 * 64 * 132 + 2 * 128 * 68 + 128 * 68) * 4;  // 172032
    const int smD = 2 * 128 * 68 * 4;                 // 69632

    cudaFuncSetAttribute(conv_theta_kernel, cudaFuncAttributeMaxDynamicSharedMemorySize, smA);
    cudaFuncSetAttribute(conv_gphi_kernel,  cudaFuncAttributeMaxDynamicSharedMemorySize, smB);
    cudaFuncSetAttribute(attn_kernel,       cudaFuncAttributeMaxDynamicSharedMemorySize, smC);
    cudaFuncSetAttribute(wconv_kernel,      cudaFuncAttributeMaxDynamicSharedMemorySize, smD);

    conv_theta_kernel<<<dim3(NQ_ / 128, B_), 256, smA>>>(x, th_w, th_b);
    conv_gphi_kernel<<<dim3(128, B_), 256, smB>>>(x, g_w, g_b, ph_w, ph_b);
    attn_kernel<<<dim3(NQ_ / 128, B_), 256, smC>>>();
    wconv_kernel<<<dim3(NQ_ / 128, C_ / 128, B_), 256, smD>>>(x, w_w, w_b,
                                                              bn_g, bn_b, bn_m, bn_v, out);
}

// round 6
// speedup vs baseline: 4.7421x; 1.0399x over previous
#include <cuda_runtime.h>
#include <math.h>
#include <stdint.h>

#define B_  4
#define C_  256
#define CI_ 128
#define NQ_ 8192
#define NKV_ 2048

// scratch (no cudaMalloc allowed)
__device__ float d_xT  [(size_t)B_ * NQ_ * C_];     // (b, n, c)    tf32-rounded
__device__ float twr   [CI_ * C_];                  // rounded theta_w
__device__ float gwr   [CI_ * C_];                  // rounded g_w
__device__ float pwr   [CI_ * C_];                  // rounded phi_w
__device__ float wwr   [C_ * CI_];                  // rounded w_w
__device__ float d_theta[(size_t)B_ * NQ_ * CI_];   // (b, n, ci)   tf32-rounded
__device__ float d_key  [(size_t)B_ * NKV_ * CI_];  // (b, m, ci)   tf32-rounded
__device__ float d_valT [(size_t)B_ * CI_ * NKV_];  // (b, ci, m)   tf32-rounded
__device__ float d_yy   [(size_t)B_ * NQ_ * CI_];   // (b, n, ci)   tf32-rounded

__device__ __forceinline__ float f2tf(float f) {
    uint32_t u;
    asm("cvt.rna.tf32.f32 %0, %1;" : "=r"(u) : "f"(f));
    return __uint_as_float(u);
}

__device__ __forceinline__ void mma_tf32(float* c, const uint32_t* a, const uint32_t* b) {
    asm volatile(
        "mma.sync.aligned.m16n8k8.row.col.f32.tf32.tf32.f32 "
        "{%0,%1,%2,%3}, {%4,%5,%6,%7}, {%8,%9}, {%0,%1,%2,%3};"
        : "+f"(c[0]), "+f"(c[1]), "+f"(c[2]), "+f"(c[3])
        : "r"(a[0]), "r"(a[1]), "r"(a[2]), "r"(a[3]), "r"(b[0]), "r"(b[1]));
}

__device__ __forceinline__ void ldsm_x4(uint32_t* r, uint32_t a) {
    asm volatile("ldmatrix.sync.aligned.m8n8.x4.shared.b16 {%0,%1,%2,%3}, [%4];"
                 : "=r"(r[0]), "=r"(r[1]), "=r"(r[2]), "=r"(r[3]) : "r"(a));
}

__device__ __forceinline__ void cpa(uint32_t dst, const float* src) {
    asm volatile("cp.async.cg.shared.global [%0], [%1], 16;" :: "r"(dst), "l"(src));
}
#define CP_COMMIT() asm volatile("cp.async.commit_group;")
#define CP_WAIT0()  asm volatile("cp.async.wait_group 0;")

// ---------------------------------------------------------------------------
// Prep 1: transpose + tf32-round x (b,c,n) -> d_xT (b,n,c)
// grid (NQ/64, C/64, B), 256 threads.
// ---------------------------------------------------------------------------
__global__ void __launch_bounds__(256) prep_x_kernel(const float* __restrict__ x) {
    __shared__ float Ts[64 * 65];
    const int b = blockIdx.z, cb = blockIdx.y * 64, nb = blockIdx.x * 64;
    const int tid = threadIdx.x;
#pragma unroll
    for (int u = 0; u < 4; u++) {
        int idx = u * 256 + tid;
        int cc = idx >> 4, j4 = idx & 15;
        float4 v = *(const float4*)&x[((size_t)b * C_ + cb + cc) * NQ_ + nb + j4 * 4];
        Ts[(j4 * 4 + 0) * 65 + cc] = f2tf(v.x);
        Ts[(j4 * 4 + 1) * 65 + cc] = f2tf(v.y);
        Ts[(j4 * 4 + 2) * 65 + cc] = f2tf(v.z);
        Ts[(j4 * 4 + 3) * 65 + cc] = f2tf(v.w);
    }
    __syncthreads();
#pragma unroll
    for (int u = 0; u < 4; u++) {
        int idx = u * 256 + tid;
        int nn = idx >> 4, c4 = idx & 15;
        float4 v = {Ts[nn * 65 + c4 * 4], Ts[nn * 65 + c4 * 4 + 1],
                    Ts[nn * 65 + c4 * 4 + 2], Ts[nn * 65 + c4 * 4 + 3]};
        *(float4*)&d_xT[((size_t)b * NQ_ + nb + nn) * C_ + cb + c4 * 4] = v;
    }
}

// ---------------------------------------------------------------------------
// Prep 2: tf32-round all weights. grid 32 x 256; each array 32768 floats.
// ---------------------------------------------------------------------------
__global__ void __launch_bounds__(256) prep_w_kernel(
        const float* __restrict__ tw, const float* __restrict__ gw,
        const float* __restrict__ pw, const float* __restrict__ ww) {
    int i = (blockIdx.x * 256 + threadIdx.x) * 4;
    float4 v;
    v = *(const float4*)&tw[i];
    v.x = f2tf(v.x); v.y = f2tf(v.y); v.z = f2tf(v.z); v.w = f2tf(v.w);
    *(float4*)&twr[i] = v;
    v = *(const float4*)&gw[i];
    v.x = f2tf(v.x); v.y = f2tf(v.y); v.z = f2tf(v.z); v.w = f2tf(v.w);
    *(float4*)&gwr[i] = v;
    v = *(const float4*)&pw[i];
    v.x = f2tf(v.x); v.y = f2tf(v.y); v.z = f2tf(v.z); v.w = f2tf(v.w);
    *(float4*)&pwr[i] = v;
    v = *(const float4*)&ww[i];
    v.x = f2tf(v.x); v.y = f2tf(v.y); v.z = f2tf(v.z); v.w = f2tf(v.w);
    *(float4*)&wwr[i] = v;
}

// ---------------------------------------------------------------------------
// Kernel A: theta conv. 128n x 128o tile, K=256 in 4 chunks, cp.async db + ldsm.
// grid (NQ/128, B), 256 threads.
// smem floats: X0@0 X1@8704 W0@17408 W1@26112  (each [128][68])
// ---------------------------------------------------------------------------
__global__ void __launch_bounds__(256) conv_theta_kernel(const float* __restrict__ tb) {
    extern __shared__ float sm[];
    const int b = blockIdx.y;
    const int nbase = blockIdx.x * 128;
    const int tid = threadIdx.x;
    const int warp = tid >> 5, lane = tid & 31;
    const int g = lane >> 2, q4 = lane & 3;
    const int m0 = (warp >> 2) * 64;
    const int n0 = (warp & 3) * 32;
    const uint32_t smb = (uint32_t)__cvta_generic_to_shared(sm);
    const uint32_t XB[2] = {0u, 8704u}, WB[2] = {17408u, 26112u};
    const int aOff = ((lane & 7) + ((lane >> 3) & 1) * 8) * 68 + ((lane >> 4) ? 4 : 0);
    const int bOff = ((lane & 7) + ((lane >> 4) & 1) * 8) * 68 + ((lane >> 3) & 1) * 4;

    float acc[4][4][4];
#pragma unroll
    for (int i = 0; i < 4; i++)
#pragma unroll
        for (int j = 0; j < 4; j++)
#pragma unroll
            for (int k = 0; k < 4; k++) acc[i][j][k] = 0.f;

    const float* xb = &d_xT[((size_t)b * NQ_ + nbase) * C_];

    // prefetch chunk 0
#pragma unroll
    for (int u = 0; u < 8; u++) {
        int idx = u * 256 + tid;
        int r = idx >> 4, c4 = idx & 15;
        cpa(smb + (XB[0] + r * 68 + c4 * 4) * 4u, xb + (size_t)r * C_ + c4 * 4);
        cpa(smb + (WB[0] + r * 68 + c4 * 4) * 4u, &twr[r * C_ + c4 * 4]);
    }
    CP_COMMIT();

    for (int ch = 0; ch < 4; ch++) {
        CP_WAIT0();
        __syncthreads();
        if (ch < 3) {
            int c0 = (ch + 1) * 64, buf = (ch + 1) & 1;
#pragma unroll
            for (int u = 0; u < 8; u++) {
                int idx = u * 256 + tid;
                int r = idx >> 4, c4 = idx & 15;
                cpa(smb + (XB[buf] + r * 68 + c4 * 4) * 4u, xb + (size_t)r * C_ + c0 + c4 * 4);
                cpa(smb + (WB[buf] + r * 68 + c4 * 4) * 4u, &twr[r * C_ + c0 + c4 * 4]);
            }
            CP_COMMIT();
        }
        const uint32_t Xa = smb + (XB[ch & 1] + aOff) * 4u;
        const uint32_t Wa = smb + (WB[ch & 1] + bOff) * 4u;
#pragma unroll
        for (int ks = 0; ks < 8; ks++) {
            uint32_t a[4][4];
#pragma unroll
            for (int mt = 0; mt < 4; mt++)
                ldsm_x4(a[mt], Xa + (uint32_t)((m0 + mt * 16) * 68 + ks * 8) * 4u);
#pragma unroll
            for (int np = 0; np < 2; np++) {
                uint32_t bb[4];
                ldsm_x4(bb, Wa + (uint32_t)((n0 + np * 16) * 68 + ks * 8) * 4u);
#pragma unroll
                for (int mt = 0; mt < 4; mt++) {
                    mma_tf32(acc[mt][2 * np], a[mt], bb);
                    mma_tf32(acc[mt][2 * np + 1], a[mt], bb + 2);
                }
            }
        }
    }
#pragma unroll
    for (int nt = 0; nt < 4; nt++) {
        int o = n0 + nt * 8 + 2 * q4;
        float b0 = tb[o], b1 = tb[o + 1];
#pragma unroll
        for (int mt = 0; mt < 4; mt++) {
            size_t r = (size_t)b * NQ_ + nbase + m0 + mt * 16 + g;
            float2 v0 = {f2tf(acc[mt][nt][0] + b0), f2tf(acc[mt][nt][1] + b1)};
            float2 v1 = {f2tf(acc[mt][nt][2] + b0), f2tf(acc[mt][nt][3] + b1)};
            *(float2*)&d_theta[r * CI_ + o] = v0;
            *(float2*)&d_theta[(r + 8) * CI_ + o] = v1;
        }
    }
}

// ---------------------------------------------------------------------------
// Kernel B: g/phi conv + maxpool(1,2,2). 64n x 128o, K=256 in 4 chunks.
// grid (128, B), 256 threads.
// smem floats: X0@0 X1@4352 Wg0@8704 Wg1@17408 Wp0@26112 Wp1@34816
// ---------------------------------------------------------------------------
__global__ void __launch_bounds__(256) conv_gphi_kernel(
        const float* __restrict__ gb, const float* __restrict__ pb) {
    extern __shared__ float sm[];
    const int b = blockIdx.y;
    const int t = blockIdx.x >> 4, hp = blockIdx.x & 15;
    const int nbase = t * 1024 + hp * 64;
    const int tid = threadIdx.x;
    const int warp = tid >> 5, lane = tid & 31;
    const int g = lane >> 2, q4 = lane & 3;
    const int m0 = (warp >> 2) * 32;
    const int n0 = (warp & 3) * 32;
    const uint32_t smb = (uint32_t)__cvta_generic_to_shared(sm);
    const uint32_t XB[2] = {0u, 4352u}, GB[2] = {8704u, 17408u}, PB[2] = {26112u, 34816u};
    const int aOff = ((lane & 7) + ((lane >> 3) & 1) * 8) * 68 + ((lane >> 4) ? 4 : 0);
    const int bOff = ((lane & 7) + ((lane >> 4) & 1) * 8) * 68 + ((lane >> 3) & 1) * 4;

    float ag[2][4][4], ap[2][4][4];
#pragma unroll
    for (int i = 0; i < 2; i++)
#pragma unroll
        for (int j = 0; j < 4; j++)
#pragma unroll
            for (int k = 0; k < 4; k++) { ag[i][j][k] = 0.f; ap[i][j][k] = 0.f; }

    const float* xb = &d_xT[((size_t)b * NQ_ + nbase) * C_];

#pragma unroll
    for (int u = 0; u < 4; u++) {
        int idx = u * 256 + tid;
        int r = idx >> 4, c4 = idx & 15;
        cpa(smb + (XB[0] + r * 68 + c4 * 4) * 4u, xb + (size_t)r * C_ + c4 * 4);
    }
#pragma unroll
    for (int u = 0; u < 8; u++) {
        int idx = u * 256 + tid;
        int r = idx >> 4, c4 = idx & 15;
        cpa(smb + (GB[0] + r * 68 + c4 * 4) * 4u, &gwr[r * C_ + c4 * 4]);
        cpa(smb + (PB[0] + r * 68 + c4 * 4) * 4u, &pwr[r * C_ + c4 * 4]);
    }
    CP_COMMIT();

    for (int ch = 0; ch < 4; ch++) {
        CP_WAIT0();
        __syncthreads();
        if (ch < 3) {
            int c0 = (ch + 1) * 64, buf = (ch + 1) & 1;
#pragma unroll
            for (int u = 0; u < 4; u++) {
                int idx = u * 256 + tid;
                int r = idx >> 4, c4 = idx & 15;
                cpa(smb + (XB[buf] + r * 68 + c4 * 4) * 4u, xb + (size_t)r * C_ + c0 + c4 * 4);
            }
#pragma unroll
            for (int u = 0; u < 8; u++) {
                int idx = u * 256 + tid;
                int r = idx >> 4, c4 = idx & 15;
                cpa(smb + (GB[buf] + r * 68 + c4 * 4) * 4u, &gwr[r * C_ + c0 + c4 * 4]);
                cpa(smb + (PB[buf] + r * 68 + c4 * 4) * 4u, &pwr[r * C_ + c0 + c4 * 4]);
            }
            CP_COMMIT();
        }
        const uint32_t Xa = smb + (XB[ch & 1] + aOff) * 4u;
        const uint32_t Ga = smb + (GB[ch & 1] + bOff) * 4u;
        const uint32_t Pa = smb + (PB[ch & 1] + bOff) * 4u;
#pragma unroll
        for (int ks = 0; ks < 8; ks++) {
            uint32_t a[2][4];
#pragma unroll
            for (int mt = 0; mt < 2; mt++)
                ldsm_x4(a[mt], Xa + (uint32_t)((m0 + mt * 16) * 68 + ks * 8) * 4u);
#pragma unroll
            for (int np = 0; np < 2; np++) {
                uint32_t bg_[4], bp_[4];
                ldsm_x4(bg_, Ga + (uint32_t)((n0 + np * 16) * 68 + ks * 8) * 4u);
                ldsm_x4(bp_, Pa + (uint32_t)((n0 + np * 16) * 68 + ks * 8) * 4u);
#pragma unroll
                for (int mt = 0; mt < 2; mt++) {
                    mma_tf32(ag[mt][2 * np], a[mt], bg_);
                    mma_tf32(ag[mt][2 * np + 1], a[mt], bg_ + 2);
                    mma_tf32(ap[mt][2 * np], a[mt], bp_);
                    mma_tf32(ap[mt][2 * np + 1], a[mt], bp_ + 2);
                }
            }
        }
    }
    // stage raw S tiles, pool, write
    __syncthreads();
    float* Sg = sm;                 // [64][132]
    float* Sp = sm + 64 * 132;      // [64][132]
    float* Pv = sm + 2 * 64 * 132;  // [128][20]
#pragma unroll
    for (int mt = 0; mt < 2; mt++) {
#pragma unroll
        for (int nt = 0; nt < 4; nt++) {
            int r = m0 + mt * 16 + g;
            int o = n0 + nt * 8 + 2 * q4;
            *(float2*)&Sg[r * 132 + o] = *(float2*)&ag[mt][nt][0];
            *(float2*)&Sg[(r + 8) * 132 + o] = *(float2*)&ag[mt][nt][2];
            *(float2*)&Sp[r * 132 + o] = *(float2*)&ap[mt][nt][0];
            *(float2*)&Sp[(r + 8) * 132 + o] = *(float2*)&ap[mt][nt][2];
        }
    }
    __syncthreads();
    const int mb = t * 256 + hp * 16;
#pragma unroll
    for (int u = 0; u < 2; u++) {
        int idx = u * 256 + tid;
        int p = idx >> 5, o4 = (idx & 31) * 4;
        float4 bgv = *(const float4*)&gb[o4];
        float4 bpv = *(const float4*)&pb[o4];
        float4 r0, r1, r2, r3;
        r0 = *(float4*)&Sp[(2 * p) * 132 + o4];
        r1 = *(float4*)&Sp[(2 * p + 1) * 132 + o4];
        r2 = *(float4*)&Sp[(32 + 2 * p) * 132 + o4];
        r3 = *(float4*)&Sp[(33 + 2 * p) * 132 + o4];
        float4 ko;
        ko.x = f2tf(fmaxf(fmaxf(r0.x, r1.x), fmaxf(r2.x, r3.x)) + bpv.x);
        ko.y = f2tf(fmaxf(fmaxf(r0.y, r1.y), fmaxf(r2.y, r3.y)) + bpv.y);
        ko.z = f2tf(fmaxf(fmaxf(r0.z, r1.z), fmaxf(r2.z, r3.z)) + bpv.z);
        ko.w = f2tf(fmaxf(fmaxf(r0.w, r1.w), fmaxf(r2.w, r3.w)) + bpv.w);
        *(float4*)&d_key[((size_t)b * NKV_ + mb + p) * CI_ + o4] = ko;
        r0 = *(float4*)&Sg[(2 * p) * 132 + o4];
        r1 = *(float4*)&Sg[(2 * p + 1) * 132 + o4];
        r2 = *(float4*)&Sg[(32 + 2 * p) * 132 + o4];
        r3 = *(float4*)&Sg[(33 + 2 * p) * 132 + o4];
        Pv[(o4 + 0) * 20 + p] = f2tf(fmaxf(fmaxf(r0.x, r1.x), fmaxf(r2.x, r3.x)) + bgv.x);
        Pv[(o4 + 1) * 20 + p] = f2tf(fmaxf(fmaxf(r0.y, r1.y), fmaxf(r2.y, r3.y)) + bgv.y);
        Pv[(o4 + 2) * 20 + p] = f2tf(fmaxf(fmaxf(r0.z, r1.z), fmaxf(r2.z, r3.z)) + bgv.z);
        Pv[(o4 + 3) * 20 + p] = f2tf(fmaxf(fmaxf(r0.w, r1.w), fmaxf(r2.w, r3.w)) + bgv.w);
    }
    __syncthreads();
#pragma unroll
    for (int u = 0; u < 2; u++) {
        int idx = u * 256 + tid;
        int ci = idx >> 2, j = (idx & 3) * 4;
        float4 v = {Pv[ci * 20 + j], Pv[ci * 20 + j + 1],
                    Pv[ci * 20 + j + 2], Pv[ci * 20 + j + 3]};
        *(float4*)&d_valT[((size_t)b * CI_ + ci) * NKV_ + mb + j] = v;
    }
}

// ---------------------------------------------------------------------------
// Kernel C: flash attention (unchanged core; tf32-rounded d_yy writes).
// smem floats: K0[64][132]@0  K1@8448  V0[128][68]@16896  V1@25600  Ps[128][68]@34304
// ---------------------------------------------------------------------------
__device__ __forceinline__ void cp_tile(uint32_t kdst, uint32_t vdst,
        const float* __restrict__ keyb, const float* __restrict__ valb,
        int mbase, int tid) {
#pragma unroll
    for (int u = 0; u < 8; u++) {
        int idx = u * 256 + tid;
        int r = idx >> 5, c = idx & 31;
        cpa(kdst + (uint32_t)(r * 132 + c * 4) * 4u, keyb + (size_t)(mbase + r) * CI_ + c * 4);
    }
#pragma unroll
    for (int u = 0; u < 8; u++) {
        int idx = u * 256 + tid;
        int r = idx >> 4, c = idx & 15;
        cpa(vdst + (uint32_t)(r * 68 + c * 4) * 4u, valb + (size_t)r * NKV_ + mbase + c * 4);
    }
}

__global__ void __launch_bounds__(256, 1) attn_kernel() {
    extern __shared__ float sm[];
    const int b = blockIdx.y;
    const int qbase = blockIdx.x * 128;
    const int tid = threadIdx.x;
    const int warp = tid >> 5;
    const int lane = tid & 31;
    const int g = lane >> 2, q4 = lane & 3;
    const int r0 = warp * 16 + g;
    const uint32_t smb = (uint32_t)__cvta_generic_to_shared(sm);

    float* Ps = sm + 34304;

    {
        const float* src = &d_theta[((size_t)b * NQ_ + qbase) * CI_];
#pragma unroll
        for (int u = 0; u < 16; u++) {
            int idx = u * 256 + tid;
            int r = idx >> 5, c4 = idx & 31;
            *(float4*)&sm[r * 132 + c4 * 4] = *(const float4*)&src[r * CI_ + c4 * 4];
        }
    }
    __syncthreads();
    uint32_t qfrag[16][4];
    {
        uint32_t qa = smb + (uint32_t)((warp * 16 + (lane & 7) + ((lane >> 3) & 1) * 8) * 132
                                       + ((lane >> 4) ? 4 : 0)) * 4u;
#pragma unroll
        for (int ks = 0; ks < 16; ks++) ldsm_x4(qfrag[ks], qa + ks * 32);
    }
    __syncthreads();

    const uint32_t kK = ((lane & 7) + ((lane >> 4) & 1) * 8) * 132 + ((lane >> 3) & 1) * 4;
    const uint32_t kV = ((lane & 7) + ((lane >> 4) & 1) * 8) * 68 + ((lane >> 3) & 1) * 4;
    const uint32_t pa = (uint32_t)((warp * 16 + (lane & 7) + ((lane >> 3) & 1) * 8) * 68
                                   + ((lane >> 4) ? 4 : 0));
    const uint32_t KbA[2] = {smb, smb + 8448u * 4};
    const uint32_t VbA[2] = {smb + 16896u * 4, smb + 25600u * 4};
    const uint32_t PsA = smb + 34304u * 4;

    const float* keyb = &d_key[(size_t)b * NKV_ * CI_];
    const float* valb = &d_valT[(size_t)b * CI_ * NKV_];

    cp_tile(KbA[0], VbA[0], keyb, valb, 0, tid);
    CP_COMMIT();

    float m[2] = {-3.0e38f, -3.0e38f}, l[2] = {0.f, 0.f};
    float oacc[16][4];
#pragma unroll
    for (int i = 0; i < 16; i++)
#pragma unroll
        for (int j = 0; j < 4; j++) oacc[i][j] = 0.f;

    for (int mt = 0; mt < NKV_ / 64; mt++) {
        CP_WAIT0();
        __syncthreads();
        if (mt + 1 < NKV_ / 64) {
            cp_tile(KbA[(mt + 1) & 1], VbA[(mt + 1) & 1], keyb, valb, (mt + 1) * 64, tid);
            CP_COMMIT();
        }
        const uint32_t Ka = KbA[mt & 1] + kK * 4;
        const uint32_t Va = VbA[mt & 1] + kV * 4;

        float sacc[8][4];
#pragma unroll
        for (int i = 0; i < 8; i++)
#pragma unroll
            for (int j = 0; j < 4; j++) sacc[i][j] = 0.f;

#pragma unroll
        for (int ks = 0; ks < 16; ks++) {
#pragma unroll
            for (int ntp = 0; ntp < 4; ntp++) {
                uint32_t bb[4];
                ldsm_x4(bb, Ka + (uint32_t)(ntp * 16 * 132 + ks * 8) * 4u);
                mma_tf32(sacc[2 * ntp], qfrag[ks], bb);
                mma_tf32(sacc[2 * ntp + 1], qfrag[ks], bb + 2);
            }
        }

#pragma unroll
        for (int h = 0; h < 2; h++) {
            float tmax = -3.0e38f;
#pragma unroll
            for (int nt = 0; nt < 8; nt++)
                tmax = fmaxf(tmax, fmaxf(sacc[nt][2 * h], sacc[nt][2 * h + 1]));
            tmax = fmaxf(tmax, __shfl_xor_sync(0xffffffffu, tmax, 1));
            tmax = fmaxf(tmax, __shfl_xor_sync(0xffffffffu, tmax, 2));
            float nm = fmaxf(m[h], tmax);
            float fac = __expf(m[h] - nm);
            float s = 0.f;
#pragma unroll
            for (int nt = 0; nt < 8; nt++) {
                float e0 = __expf(sacc[nt][2 * h] - nm);
                float e1 = __expf(sacc[nt][2 * h + 1] - nm);
                sacc[nt][2 * h] = e0; sacc[nt][2 * h + 1] = e1;
                s += e0 + e1;
            }
            s += __shfl_xor_sync(0xffffffffu, s, 1);
            s += __shfl_xor_sync(0xffffffffu, s, 2);
            l[h] = l[h] * fac + s;
            m[h] = nm;
#pragma unroll
            for (int ot = 0; ot < 16; ot++) {
                oacc[ot][2 * h]     *= fac;
                oacc[ot][2 * h + 1] *= fac;
            }
        }

#pragma unroll
        for (int nt = 0; nt < 8; nt++) {
            int cb = nt * 8 + 2 * q4;
            Ps[r0 * 68 + cb]           = f2tf(sacc[nt][0]);
            Ps[r0 * 68 + cb + 1]       = f2tf(sacc[nt][1]);
            Ps[(r0 + 8) * 68 + cb]     = f2tf(sacc[nt][2]);
            Ps[(r0 + 8) * 68 + cb + 1] = f2tf(sacc[nt][3]);
        }
        __syncwarp();

#pragma unroll
        for (int ks = 0; ks < 8; ks++) {
            uint32_t a[4];
            ldsm_x4(a, PsA + (pa + ks * 8) * 4u);
#pragma unroll
            for (int ntp = 0; ntp < 8; ntp++) {
                uint32_t bb[4];
                ldsm_x4(bb, Va + (uint32_t)(ntp * 16 * 68 + ks * 8) * 4u);
                mma_tf32(oacc[2 * ntp], a, bb);
                mma_tf32(oacc[2 * ntp + 1], a, bb + 2);
            }
        }
    }

    float inv0 = 1.f / l[0], inv1 = 1.f / l[1];
    size_t row0 = (size_t)b * NQ_ + qbase + r0;
#pragma unroll
    for (int nt = 0; nt < 16; nt++) {
        int ci = nt * 8 + 2 * q4;
        float2 v0 = {f2tf(oacc[nt][0] * inv0), f2tf(oacc[nt][1] * inv0)};
        float2 v1 = {f2tf(oacc[nt][2] * inv1), f2tf(oacc[nt][3] * inv1)};
        *(float2*)&d_yy[row0 * CI_ + ci] = v0;
        *(float2*)&d_yy[(row0 + 8) * CI_ + ci] = v1;
    }
}

// ---------------------------------------------------------------------------
// Kernel D: wconv + BN + residual. 128co x 128n, K=128 in 2 chunks, db+ldsm.
// grid (NQ/128, C/128, B), 256 threads.
// smem floats: W0@0 W1@8704 Y0@17408 Y1@26112
// ---------------------------------------------------------------------------
__global__ void __launch_bounds__(256) wconv_kernel(
        const float* __restrict__ x,
        const float* __restrict__ wb,
        const float* __restrict__ bng, const float* __restrict__ bnb,
        const float* __restrict__ bnm, const float* __restrict__ bnv,
        float* __restrict__ out) {
    extern __shared__ float sm[];
    const int b = blockIdx.z;
    const int cobase = blockIdx.y * 128;
    const int nbase = blockIdx.x * 128;
    const int tid = threadIdx.x;
    const int warp = tid >> 5, lane = tid & 31;
    const int g = lane >> 2, q4 = lane & 3;
    const int m0 = (warp >> 2) * 64;
    const int n0 = (warp & 3) * 32;
    const uint32_t smb = (uint32_t)__cvta_generic_to_shared(sm);
    const uint32_t WB[2] = {0u, 8704u}, YB[2] = {17408u, 26112u};
    const int aOff = ((lane & 7) + ((lane >> 3) & 1) * 8) * 68 + ((lane >> 4) ? 4 : 0);
    const int bOff = ((lane & 7) + ((lane >> 4) & 1) * 8) * 68 + ((lane >> 3) & 1) * 4;

    float acc[4][4][4];
#pragma unroll
    for (int i = 0; i < 4; i++)
#pragma unroll
        for (int j = 0; j < 4; j++)
#pragma unroll
            for (int k = 0; k < 4; k++) acc[i][j][k] = 0.f;

    const float* yb = &d_yy[((size_t)b * NQ_ + nbase) * CI_];

#pragma unroll
    for (int u = 0; u < 8; u++) {
        int idx = u * 256 + tid;
        int r = idx >> 4, c4 = idx & 15;
        cpa(smb + (WB[0] + r * 68 + c4 * 4) * 4u, &wwr[(cobase + r) * CI_ + c4 * 4]);
        cpa(smb + (YB[0] + r * 68 + c4 * 4) * 4u, yb + (size_t)r * CI_ + c4 * 4);
    }
    CP_COMMIT();

    for (int ch = 0; ch < 2; ch++) {
        CP_WAIT0();
        __syncthreads();
        if (ch < 1) {
            int c0 = 64, buf = 1;
#pragma unroll
            for (int u = 0; u < 8; u++) {
                int idx = u * 256 + tid;
                int r = idx >> 4, c4 = idx & 15;
                cpa(smb + (WB[buf] + r * 68 + c4 * 4) * 4u, &wwr[(cobase + r) * CI_ + c0 + c4 * 4]);
                cpa(smb + (YB[buf] + r * 68 + c4 * 4) * 4u, yb + (size_t)r * CI_ + c0 + c4 * 4);
            }
            CP_COMMIT();
        }
        const uint32_t Wa = smb + (WB[ch & 1] + aOff) * 4u;
        const uint32_t Ya = smb + (YB[ch & 1] + bOff) * 4u;
#pragma unroll
        for (int ks = 0; ks < 8; ks++) {
            uint32_t a[4][4];
#pragma unroll
            for (int mt = 0; mt < 4; mt++)
                ldsm_x4(a[mt], Wa + (uint32_t)((m0 + mt * 16) * 68 + ks * 8) * 4u);
#pragma unroll
            for (int np = 0; np < 2; np++) {
                uint32_t bb[4];
                ldsm_x4(bb, Ya + (uint32_t)((n0 + np * 16) * 68 + ks * 8) * 4u);
#pragma unroll
                for (int mt = 0; mt < 4; mt++) {
                    mma_tf32(acc[mt][2 * np], a[mt], bb);
                    mma_tf32(acc[mt][2 * np + 1], a[mt], bb + 2);
                }
            }
        }
    }

    float sc[4][2], sh[4][2];
#pragma unroll
    for (int mt = 0; mt < 4; mt++)
#pragma unroll
        for (int h = 0; h < 2; h++) {
            int co = cobase + m0 + mt * 16 + g + h * 8;
            float s = bng[co] * rsqrtf(bnv[co] + 1e-5f);
            sc[mt][h] = s;
            sh[mt][h] = bnb[co] - bnm[co] * s + s * wb[co];
        }
#pragma unroll
    for (int mt = 0; mt < 4; mt++) {
#pragma unroll
        for (int nt = 0; nt < 4; nt++) {
            int n = nbase + n0 + nt * 8 + 2 * q4;
#pragma unroll
            for (int h = 0; h < 2; h++) {
                int co = cobase + m0 + mt * 16 + g + h * 8;
                size_t base = ((size_t)b * C_ + co) * NQ_ + n;
                float2 xv = *(const float2*)&x[base];
                float2 o;
                o.x = acc[mt][nt][2 * h]     * sc[mt][h] + sh[mt][h] + xv.x;
                o.y = acc[mt][nt][2 * h + 1] * sc[mt][h] + sh[mt][h] + xv.y;
                *(float2*)&out[base] = o;
            }
        }
    }
}

// ---------------------------------------------------------------------------
extern "C" void kernel_launch(void* const* d_in, const int* in_sizes, int n_in,
                              void* d_out, int out_size) {
    const float* x    = (const float*)d_in[0];
    const float* g_w  = (const float*)d_in[1];
    const float* g_b  = (const float*)d_in[2];
    const float* th_w = (const float*)d_in[3];
    const float* th_b = (const float*)d_in[4];
    const float* ph_w = (const float*)d_in[5];
    const float* ph_b = (const float*)d_in[6];
    const float* w_w  = (const float*)d_in[7];
    const float* w_b  = (const float*)d_in[8];
    const float* bn_g = (const float*)d_in[9];
    const float* bn_b = (const float*)d_in[10];
    const float* bn_m = (const float*)d_in[11];
    const float* bn_v = (const float*)d_in[12];
    float* out = (float*)d_out;

    const int smA = 4 * 128 * 68 * 4;                               // 139264
    const int smB = (2 * 64 * 68 + 4 * 128 * 68) * 4;               // 174080
    const int smC = (2 * 64 * 132 + 2 * 128 * 68 + 128 * 68) * 4;   // 172032
    const int smD = 4 * 128 * 68 * 4;                               // 139264

    cudaFuncSetAttribute(conv_theta_kernel, cudaFuncAttributeMaxDynamicSharedMemorySize, smA);
    cudaFuncSetAttribute(conv_gphi_kernel,  cudaFuncAttributeMaxDynamicSharedMemorySize, smB);
    cudaFuncSetAttribute(attn_kernel,       cudaFuncAttributeMaxDynamicSharedMemorySize, smC);
    cudaFuncSetAttribute(wconv_kernel,      cudaFuncAttributeMaxDynamicSharedMemorySize, smD);

    prep_x_kernel<<<dim3(NQ_ / 64, C_ / 64, B_), 256>>>(x);
    prep_w_kernel<<<32, 256>>>(th_w, g_w, ph_w, w_w);
    conv_theta_kernel<<<dim3(NQ_ / 128, B_), 256, smA>>>(th_b);
    conv_gphi_kernel<<<dim3(128, B_), 256, smB>>>(g_b, ph_b);
    attn_kernel<<<dim3(NQ_ / 128, B_), 256, smC>>>();
    wconv_kernel<<<dim3(NQ_ / 128, C_ / 128, B_), 256, smD>>>(x, w_b,
                                                              bn_g, bn_b, bn_m, bn_v, out);
}